// round 3
// baseline (speedup 1.0000x reference)
#include <cuda_runtime.h>
#include <math.h>

#define BB 2
#define CC 256
#define HWN 4096
#define KCN 32
#define RDN 16
#define EPSV 1e-5f

// ---------------- scratch (device globals: allocation-free rule) ----------------
__device__ float g_mean[BB*CC];
__device__ float g_gate[BB*CC];
__device__ float g_V   [BB*CC*HWN];   // [b][c][m]
__device__ float g_Q   [BB*HWN*KCN];  // [b][m][k]
__device__ float g_K   [BB*KCN*HWN];  // [b][k][m]
__device__ float g_b1r [BB*KCN*HWN];  // relu'd
__device__ float g_b2r [BB*KCN*HWN];  // relu'd
__device__ float g_b1s [BB*HWN*KCN];  // smoothed, transposed [b][n][k]
__device__ float g_b2s [BB*KCN*HWN];  // smoothed [b][k][m]
__device__ float g_ctx [BB*HWN*CC];   // [b][n][c]

typedef unsigned long long u64;

__device__ __forceinline__ void fma2(u64 &d, u64 a, u64 b){
    asm("fma.rn.f32x2 %0, %1, %2, %0;" : "+l"(d) : "l"(a), "l"(b));
}
__device__ __forceinline__ void mul2(u64 &d, u64 f){
    asm("mul.rn.f32x2 %0, %0, %1;" : "+l"(d) : "l"(f));
}
__device__ __forceinline__ u64 pack2same(float x){
    u64 r; asm("mov.b64 %0, {%1,%2};" : "=l"(r) : "f"(x), "f"(x)); return r;
}
__device__ __forceinline__ float2 unpack2(u64 v){
    float2 r; asm("mov.b64 {%0,%1}, %2;" : "=f"(r.x), "=f"(r.y) : "l"(v)); return r;
}
__device__ __forceinline__ float sigm(float x){
    return __fdividef(1.0f, 1.0f + __expf(-x));
}

// ---------------- 1) per-(b,c) spatial mean ----------------
__global__ void k_mean(const float* __restrict__ x){
    int b = blockIdx.y;
    int c = blockIdx.x*8 + (threadIdx.x>>5);
    int lane = threadIdx.x & 31;
    const float* p = x + ((size_t)(b*CC + c))*HWN;
    float s = 0.f;
    for(int i=lane;i<HWN;i+=32) s += p[i];
    #pragma unroll
    for(int o=16;o;o>>=1) s += __shfl_xor_sync(0xffffffffu, s, o);
    if(lane==0) g_mean[b*CC+c] = s * (1.0f/HWN);
}

// ---------------- 2) GatherExcite MLP -> sigmoid gate ----------------
__global__ void k_gate(const float* __restrict__ w1, const float* __restrict__ b1,
                       const float* __restrict__ w2, const float* __restrict__ b2){
    __shared__ float sm[CC];
    __shared__ float sg[RDN];
    int b = blockIdx.x, t = threadIdx.x;
    sm[t] = g_mean[b*CC + t];
    __syncthreads();
    if(t < RDN){
        float a = b1[t];
        for(int c=0;c<CC;c++) a += w1[t*CC + c]*sm[c];
        sg[t] = fmaxf(a, 0.f);
    }
    __syncthreads();
    float a = b2[t];
    #pragma unroll
    for(int r=0;r<RDN;r++) a += w2[t*RDN + r]*sg[r];
    g_gate[b*CC + t] = sigm(a);
}

// ---------------- 3) q/k/b1/b2 projections (128 out-ch GEMM, gate folded into Wk) --
__global__ void __launch_bounds__(256) k_proj_qkb(
    const float* __restrict__ x,
    const float* __restrict__ Wq, const float* __restrict__ Wk,
    const float* __restrict__ Wb1, const float* __restrict__ Wb2)
{
    __shared__ float xs[32*128];
    __shared__ float ws[128*33];
    int b  = blockIdx.y;
    int m0 = blockIdx.x*128;
    int t  = threadIdx.x;
    int to = t & 15, tm = t >> 4;

    float acc[8][8];
    #pragma unroll
    for(int i=0;i<8;i++)
        #pragma unroll
        for(int j=0;j<8;j++) acc[i][j]=0.f;

    for(int cc0=0; cc0<CC; cc0+=32){
        for(int idx=t; idx<32*128; idx+=256){
            int ci = idx>>7, m = idx&127;
            xs[ci*128 + m] = x[((size_t)(b*CC + cc0+ci))*HWN + m0 + m];
        }
        for(int idx=t; idx<128*32; idx+=256){
            int o = idx>>5, ci = idx&31;
            int cg = cc0 + ci;
            float w;
            if(o<32)       w = Wq [(o   )*CC + cg];
            else if(o<64)  w = Wk [(o-32)*CC + cg] * g_gate[b*CC + cg];
            else if(o<96)  w = Wb1[(o-64)*CC + cg];
            else           w = Wb2[(o-96)*CC + cg];
            ws[o*33 + ci] = w;
        }
        __syncthreads();
        #pragma unroll 8
        for(int ci=0;ci<32;ci++){
            float xv[8];
            #pragma unroll
            for(int j=0;j<8;j++) xv[j] = xs[ci*128 + tm*8 + j];
            #pragma unroll
            for(int i=0;i<8;i++){
                float wv = ws[(to+16*i)*33 + ci];
                #pragma unroll
                for(int j=0;j<8;j++) acc[i][j] = fmaf(wv, xv[j], acc[i][j]);
            }
        }
        __syncthreads();
    }
    #pragma unroll
    for(int i=0;i<8;i++){
        int o = to + 16*i;
        #pragma unroll
        for(int j=0;j<8;j++){
            int m = m0 + tm*8 + j;
            float v = acc[i][j];
            if(o < 32)       g_Q  [((size_t)(b*HWN+m))*KCN + o]        = v;
            else if(o < 64)  g_K  [((size_t)(b*KCN + o-32))*HWN + m]   = v;
            else if(o < 96)  g_b1r[((size_t)(b*KCN + o-64))*HWN + m]   = fmaxf(v, 0.f);
            else             g_b2r[((size_t)(b*KCN + o-96))*HWN + m]   = fmaxf(v, 0.f);
        }
    }
}

// ---------------- 4) value projection: g_V[b][c][m] ----------------
__global__ void __launch_bounds__(256) k_proj_v(
    const float* __restrict__ x, const float* __restrict__ Wv)
{
    __shared__ float xs[32*128];
    __shared__ float ws[64*33];
    int b  = blockIdx.z;
    int c0 = blockIdx.y*64;
    int m0 = blockIdx.x*128;
    int t  = threadIdx.x;
    int to = t & 15, tm = t >> 4;

    float acc[4][8];
    #pragma unroll
    for(int i=0;i<4;i++)
        #pragma unroll
        for(int j=0;j<8;j++) acc[i][j]=0.f;

    for(int cc0=0; cc0<CC; cc0+=32){
        for(int idx=t; idx<32*128; idx+=256){
            int ci = idx>>7, m = idx&127;
            xs[ci*128 + m] = x[((size_t)(b*CC + cc0+ci))*HWN + m0 + m];
        }
        for(int idx=t; idx<64*32; idx+=256){
            int o = idx>>5, ci = idx&31;
            ws[o*33 + ci] = Wv[(size_t)(c0+o)*CC + cc0 + ci];
        }
        __syncthreads();
        #pragma unroll 8
        for(int ci=0;ci<32;ci++){
            float xv[8];
            #pragma unroll
            for(int j=0;j<8;j++) xv[j] = xs[ci*128 + tm*8 + j];
            #pragma unroll
            for(int i=0;i<4;i++){
                float wv = ws[(to+16*i)*33 + ci];
                #pragma unroll
                for(int j=0;j<8;j++) acc[i][j] = fmaf(wv, xv[j], acc[i][j]);
            }
        }
        __syncthreads();
    }
    #pragma unroll
    for(int i=0;i<4;i++){
        int c = c0 + to + 16*i;
        #pragma unroll
        for(int j=0;j<8;j++)
            g_V[((size_t)(b*CC + c))*HWN + m0 + tm*8 + j] = acc[i][j];
    }
}

// ---------------- 5) 3-tap box smoothing (separable avg-pool) ----------------
__global__ void k_smooth(){
    int idx = blockIdx.x*256 + threadIdx.x;   // total BB*KCN*HWN
    int n = idx & (HWN-1);
    int k = (idx >> 12) & (KCN-1);
    int b = idx >> 17;
    size_t base = ((size_t)(b*KCN + k))*HWN + n;
    float a1 = g_b1r[base], a2 = g_b2r[base];
    if(n > 0)      { a1 += g_b1r[base-1]; a2 += g_b2r[base-1]; }
    if(n < HWN-1)  { a1 += g_b1r[base+1]; a2 += g_b2r[base+1]; }
    g_b1s[((size_t)(b*HWN + n))*KCN + k] = a1;
    g_b2s[base] = a2;
}

// ---------------- 6) fused attention (flash-style, f32x2 packed math) ----------
#define ATTN_SMEM ((64*260 + 64*65 + 32*64 + 32*64 + 64*32 + 64*32)*4)

__global__ void __launch_bounds__(256,1) k_attn(const float* __restrict__ wgb){
    extern __shared__ float sm[];
    float* vs  = sm;             // [64][260]  V tile (16B-aligned rows)
    float* ps  = vs  + 64*260;   // [64][65]   P tile
    float* ks  = ps  + 64*65;    // [32][64]
    float* b2t = ks  + 32*64;    // [32][64]
    float* qs  = b2t + 32*64;    // [64][32]
    float* b1t = qs  + 64*32;    // [64][32]

    const int b  = blockIdx.y;
    const int n0 = blockIdx.x*64;
    const int t  = threadIdx.x;
    const int tr = t >> 4, tc = t & 15;
    const int r0 = tr*4;

    for(int idx=t; idx<64*KCN; idx+=256){
        int r = idx>>5, k = idx&31;
        qs [idx] = g_Q  [((size_t)(b*HWN + n0 + r))*KCN + k];
        b1t[idx] = g_b1s[((size_t)(b*HWN + n0 + r))*KCN + k];
    }

    u64 acc[4][4][2];
    #pragma unroll
    for(int i=0;i<4;i++)
        #pragma unroll
        for(int jj=0;jj<4;jj++){ acc[i][jj][0]=0ULL; acc[i][jj][1]=0ULL; }
    float mrow[4], lrow[4];
    #pragma unroll
    for(int i=0;i<4;i++){ mrow[i] = -1e30f; lrow[i] = 0.f; }

    const float cgb = wgb[0] * (1.0f/9.0f);

    for(int tile=0; tile<HWN/64; tile++){
        __syncthreads();   // previous PV done before overwriting tiles
        const int m0g = tile*64;
        for(int idx=t; idx<KCN*64; idx+=256){
            int k = idx>>6, m = idx&63;
            ks [idx] = g_K  [((size_t)(b*KCN+k))*HWN + m0g + m];
            b2t[idx] = g_b2s[((size_t)(b*KCN+k))*HWN + m0g + m];
        }
        for(int idx=t; idx<CC*64; idx+=256){
            int c = idx>>6, m = idx&63;
            vs[m*260 + c] = g_V[((size_t)(b*CC+c))*HWN + m0g + m];
        }
        __syncthreads();

        // ---- logits: sim and pooled-bias, packed over m pairs ----
        u64 sim2[4][2], pool2[4][2];
        #pragma unroll
        for(int i=0;i<4;i++){ sim2[i][0]=sim2[i][1]=0ULL; pool2[i][0]=pool2[i][1]=0ULL; }
        #pragma unroll 8
        for(int k=0;k<KCN;k++){
            u64 kk0 = *(const u64*)&ks [k*64 + tc*4];
            u64 kk1 = *(const u64*)&ks [k*64 + tc*4 + 2];
            u64 bb0 = *(const u64*)&b2t[k*64 + tc*4];
            u64 bb1 = *(const u64*)&b2t[k*64 + tc*4 + 2];
            #pragma unroll
            for(int i=0;i<4;i++){
                u64 q2 = pack2same(qs [(r0+i)*32 + k]);
                u64 c2 = pack2same(b1t[(r0+i)*32 + k]);
                fma2(sim2[i][0],  q2, kk0);
                fma2(sim2[i][1],  q2, kk1);
                fma2(pool2[i][0], c2, bb0);
                fma2(pool2[i][1], c2, bb1);
            }
        }

        // ---- online softmax update ----
        #pragma unroll
        for(int i=0;i<4;i++){
            float2 sa = unpack2(sim2[i][0]),  sb = unpack2(sim2[i][1]);
            float2 pa = unpack2(pool2[i][0]), pb = unpack2(pool2[i][1]);
            float lg0 = sa.x * sigm(cgb*pa.x);
            float lg1 = sa.y * sigm(cgb*pa.y);
            float lg2 = sb.x * sigm(cgb*pb.x);
            float lg3 = sb.y * sigm(cgb*pb.y);
            float tmx = fmaxf(fmaxf(lg0,lg1), fmaxf(lg2,lg3));
            #pragma unroll
            for(int o=1;o<16;o<<=1) tmx = fmaxf(tmx, __shfl_xor_sync(0xffffffffu, tmx, o));
            float mnew = fmaxf(mrow[i], tmx);
            float f = __expf(mrow[i] - mnew);
            float e0 = __expf(lg0 - mnew), e1 = __expf(lg1 - mnew);
            float e2 = __expf(lg2 - mnew), e3 = __expf(lg3 - mnew);
            float ts = (e0+e1) + (e2+e3);
            #pragma unroll
            for(int o=1;o<16;o<<=1) ts += __shfl_xor_sync(0xffffffffu, ts, o);
            lrow[i] = lrow[i]*f + ts;
            mrow[i] = mnew;
            u64 f2 = pack2same(f);
            #pragma unroll
            for(int jj=0;jj<4;jj++){ mul2(acc[i][jj][0], f2); mul2(acc[i][jj][1], f2); }
            ps[(r0+i)*65 + tc*4 + 0] = e0;
            ps[(r0+i)*65 + tc*4 + 1] = e1;
            ps[(r0+i)*65 + tc*4 + 2] = e2;
            ps[(r0+i)*65 + tc*4 + 3] = e3;
        }
        __syncthreads();

        // ---- PV: acc += P @ V (packed f32x2) ----
        #pragma unroll 4
        for(int m=0;m<64;m++){
            u64 pp[4];
            #pragma unroll
            for(int i=0;i<4;i++) pp[i] = pack2same(ps[(r0+i)*65 + m]);
            #pragma unroll
            for(int jj=0;jj<4;jj++){
                const ulonglong2 v = *(const ulonglong2*)&vs[m*260 + tc*4 + 64*jj];
                #pragma unroll
                for(int i=0;i<4;i++){
                    fma2(acc[i][jj][0], pp[i], v.x);
                    fma2(acc[i][jj][1], pp[i], v.y);
                }
            }
        }
    }

    // ---- normalize + write ctx ----
    #pragma unroll
    for(int i=0;i<4;i++){
        float rl = __fdividef(1.0f, lrow[i]);
        #pragma unroll
        for(int jj=0;jj<4;jj++){
            float2 a = unpack2(acc[i][jj][0]);
            float2 c = unpack2(acc[i][jj][1]);
            float4 o4; o4.x = a.x*rl; o4.y = a.y*rl; o4.z = c.x*rl; o4.w = c.y*rl;
            *(float4*)&g_ctx[((size_t)(b*HWN + n0 + r0 + i))*CC + tc*4 + 64*jj] = o4;
        }
    }
}

// ---------------- 7) output projection + BN + ReLU + residual ----------------
__global__ void __launch_bounds__(256) k_final(
    const float* __restrict__ x, const float* __restrict__ Wo,
    const float* __restrict__ bn_scale, const float* __restrict__ bn_bias,
    const float* __restrict__ bn_mean, const float* __restrict__ bn_var,
    const float* __restrict__ gamma, float* __restrict__ out)
{
    __shared__ float cs[128*33];
    __shared__ float ws[64*33];
    int b  = blockIdx.z;
    int c0 = blockIdx.y*64;
    int m0 = blockIdx.x*128;
    int t  = threadIdx.x;
    int to = t & 15, tm = t >> 4;

    float acc[4][8];
    #pragma unroll
    for(int i=0;i<4;i++)
        #pragma unroll
        for(int j=0;j<8;j++) acc[i][j]=0.f;

    for(int ci0=0; ci0<CC; ci0+=32){
        for(int idx=t; idx<128*32; idx+=256){
            int mm = idx>>5, cc = idx&31;
            cs[mm*33 + cc] = g_ctx[((size_t)(b*HWN + m0 + mm))*CC + ci0 + cc];
        }
        for(int idx=t; idx<64*32; idx+=256){
            int o = idx>>5, ci = idx&31;
            ws[o*33 + ci] = Wo[(size_t)(c0+o)*CC + ci0 + ci];
        }
        __syncthreads();
        #pragma unroll 8
        for(int ci=0;ci<32;ci++){
            float xv[8];
            #pragma unroll
            for(int j=0;j<8;j++) xv[j] = cs[(tm*8+j)*33 + ci];
            #pragma unroll
            for(int i=0;i<4;i++){
                float wv = ws[(to+16*i)*33 + ci];
                #pragma unroll
                for(int j=0;j<8;j++) acc[i][j] = fmaf(wv, xv[j], acc[i][j]);
            }
        }
        __syncthreads();
    }

    float gm = gamma[0];
    #pragma unroll
    for(int i=0;i<4;i++){
        int c = c0 + to + 16*i;
        float scl = bn_scale[c] * rsqrtf(bn_var[c] + EPSV);
        float mu  = bn_mean[c];
        float bi  = bn_bias[c];
        #pragma unroll
        for(int j=0;j<8;j++){
            size_t idx = ((size_t)(b*CC + c))*HWN + m0 + tm*8 + j;
            float y = (acc[i][j] - mu)*scl + bi;
            y = fmaxf(y, 0.f);
            out[idx] = gm*y + x[idx];
        }
    }
}

// ---------------- launch ----------------
extern "C" void kernel_launch(void* const* d_in, const int* in_sizes, int n_in,
                              void* d_out, int out_size){
    (void)in_sizes; (void)n_in; (void)out_size;
    const float* x        = (const float*)d_in[0];
    const float* Wq       = (const float*)d_in[1];
    const float* Wk       = (const float*)d_in[2];
    const float* Wv       = (const float*)d_in[3];
    const float* Wb1      = (const float*)d_in[4];
    const float* Wb2      = (const float*)d_in[5];
    const float* w_gb     = (const float*)d_in[6];
    const float* ge_w1    = (const float*)d_in[7];
    const float* ge_b1    = (const float*)d_in[8];
    const float* ge_w2    = (const float*)d_in[9];
    const float* ge_b2    = (const float*)d_in[10];
    const float* Wo       = (const float*)d_in[11];
    const float* bn_scale = (const float*)d_in[12];
    const float* bn_bias  = (const float*)d_in[13];
    const float* bn_mean  = (const float*)d_in[14];
    const float* bn_var   = (const float*)d_in[15];
    const float* gamma    = (const float*)d_in[16];
    float* out = (float*)d_out;

    cudaFuncSetAttribute(k_attn, cudaFuncAttributeMaxDynamicSharedMemorySize, ATTN_SMEM);

    k_mean    <<<dim3(CC/8, BB), 256>>>(x);
    k_gate    <<<BB, 256>>>(ge_w1, ge_b1, ge_w2, ge_b2);
    k_proj_qkb<<<dim3(HWN/128, BB), 256>>>(x, Wq, Wk, Wb1, Wb2);
    k_proj_v  <<<dim3(HWN/128, CC/64, BB), 256>>>(x, Wv);
    k_smooth  <<<(BB*KCN*HWN)/256, 256>>>();
    k_attn    <<<dim3(HWN/64, BB), 256, ATTN_SMEM>>>(w_gb);
    k_final   <<<dim3(HWN/128, CC/64, BB), 256>>>(x, Wo, bn_scale, bn_bias,
                                                  bn_mean, bn_var, gamma, out);
}

// round 5
// speedup vs baseline: 1.5259x; 1.5259x over previous
#include <cuda_runtime.h>
#include <math.h>

#define BB 2
#define CC 256
#define HWN 4096
#define KCN 32
#define RDN 16
#define EPSV 1e-5f
#define NT (HWN/64)

// ---------------- scratch (device globals: allocation-free rule) ----------------
__device__ float g_mean[BB*CC];
__device__ float g_gate[BB*CC];
__device__ float g_Vt  [BB*HWN*CC];   // [b][m][c]  (transposed so cp.async needs no transpose)
__device__ float g_Q   [BB*HWN*KCN];  // [b][m][k]
__device__ float g_K   [BB*KCN*HWN];  // [b][k][m]
__device__ float g_b1r [BB*KCN*HWN];
__device__ float g_b2r [BB*KCN*HWN];
__device__ float g_b1s [BB*HWN*KCN];  // smoothed, transposed [b][n][k]
__device__ float g_b2s [BB*KCN*HWN];  // smoothed [b][k][m]
__device__ float g_ctx [BB*HWN*CC];   // [b][n][c]

typedef unsigned long long u64;
typedef unsigned int u32;

__device__ __forceinline__ void fma2(u64 &d, u64 a, u64 b){
    asm("fma.rn.f32x2 %0, %1, %2, %0;" : "+l"(d) : "l"(a), "l"(b));
}
__device__ __forceinline__ u64 pack2same(float x){
    u64 r; asm("mov.b64 %0, {%1,%2};" : "=l"(r) : "f"(x), "f"(x)); return r;
}
__device__ __forceinline__ float2 unpack2(u64 v){
    float2 r; asm("mov.b64 {%0,%1}, %2;" : "=f"(r.x), "=f"(r.y) : "l"(v)); return r;
}
__device__ __forceinline__ float sigm(float x){
    return __fdividef(1.0f, 1.0f + __expf(-x));
}
__device__ __forceinline__ void cpa16(u32 dst, const float* src){
    asm volatile("cp.async.ca.shared.global [%0], [%1], 16;" :: "r"(dst), "l"(src));
}
__device__ __forceinline__ void cpa_commit(){ asm volatile("cp.async.commit_group;"); }

// ---------------- 1) per-(b,c) spatial mean ----------------
__global__ void k_mean(const float* __restrict__ x){
    int b = blockIdx.y;
    int c = blockIdx.x*8 + (threadIdx.x>>5);
    int lane = threadIdx.x & 31;
    const float* p = x + ((size_t)(b*CC + c))*HWN;
    float s = 0.f;
    for(int i=lane;i<HWN;i+=32) s += p[i];
    #pragma unroll
    for(int o=16;o;o>>=1) s += __shfl_xor_sync(0xffffffffu, s, o);
    if(lane==0) g_mean[b*CC+c] = s * (1.0f/HWN);
}

// ---------------- 2) GatherExcite MLP -> sigmoid gate ----------------
__global__ void k_gate(const float* __restrict__ w1, const float* __restrict__ b1,
                       const float* __restrict__ w2, const float* __restrict__ b2){
    __shared__ float sm[CC];
    __shared__ float sg[RDN];
    int b = blockIdx.x, t = threadIdx.x;
    sm[t] = g_mean[b*CC + t];
    __syncthreads();
    if(t < RDN){
        float a = b1[t];
        for(int c=0;c<CC;c++) a += w1[t*CC + c]*sm[c];
        sg[t] = fmaxf(a, 0.f);
    }
    __syncthreads();
    float a = b2[t];
    #pragma unroll
    for(int r=0;r<RDN;r++) a += w2[t*RDN + r]*sg[r];
    g_gate[b*CC + t] = sigm(a);
}

// ---------------- 3) q/k/b1/b2 projections ----------------
__global__ void __launch_bounds__(256) k_proj_qkb(
    const float* __restrict__ x,
    const float* __restrict__ Wq, const float* __restrict__ Wk,
    const float* __restrict__ Wb1, const float* __restrict__ Wb2)
{
    __shared__ float xs[32*128];
    __shared__ float ws[128*33];
    int b  = blockIdx.y;
    int m0 = blockIdx.x*128;
    int t  = threadIdx.x;
    int to = t & 15, tm = t >> 4;

    float acc[8][8];
    #pragma unroll
    for(int i=0;i<8;i++)
        #pragma unroll
        for(int j=0;j<8;j++) acc[i][j]=0.f;

    for(int cc0=0; cc0<CC; cc0+=32){
        for(int idx=t; idx<32*128; idx+=256){
            int ci = idx>>7, m = idx&127;
            xs[ci*128 + m] = x[((size_t)(b*CC + cc0+ci))*HWN + m0 + m];
        }
        for(int idx=t; idx<128*32; idx+=256){
            int o = idx>>5, ci = idx&31;
            int cg = cc0 + ci;
            float w;
            if(o<32)       w = Wq [(o   )*CC + cg];
            else if(o<64)  w = Wk [(o-32)*CC + cg] * g_gate[b*CC + cg];
            else if(o<96)  w = Wb1[(o-64)*CC + cg];
            else           w = Wb2[(o-96)*CC + cg];
            ws[o*33 + ci] = w;
        }
        __syncthreads();
        #pragma unroll 8
        for(int ci=0;ci<32;ci++){
            float xv[8];
            #pragma unroll
            for(int j=0;j<8;j++) xv[j] = xs[ci*128 + tm*8 + j];
            #pragma unroll
            for(int i=0;i<8;i++){
                float wv = ws[(to+16*i)*33 + ci];
                #pragma unroll
                for(int j=0;j<8;j++) acc[i][j] = fmaf(wv, xv[j], acc[i][j]);
            }
        }
        __syncthreads();
    }
    #pragma unroll
    for(int i=0;i<8;i++){
        int o = to + 16*i;
        #pragma unroll
        for(int j=0;j<8;j++){
            int m = m0 + tm*8 + j;
            float v = acc[i][j];
            if(o < 32)       g_Q  [((size_t)(b*HWN+m))*KCN + o]        = v;
            else if(o < 64)  g_K  [((size_t)(b*KCN + o-32))*HWN + m]   = v;
            else if(o < 96)  g_b1r[((size_t)(b*KCN + o-64))*HWN + m]   = fmaxf(v, 0.f);
            else             g_b2r[((size_t)(b*KCN + o-96))*HWN + m]   = fmaxf(v, 0.f);
        }
    }
}

// ---------------- 4) value projection -> transposed g_Vt[b][m][c] ----------------
__global__ void __launch_bounds__(256) k_proj_v(
    const float* __restrict__ x, const float* __restrict__ Wv)
{
    __shared__ float xs[32*128];
    __shared__ float ws[64*33];
    int b  = blockIdx.z;
    int c0 = blockIdx.y*64;
    int m0 = blockIdx.x*128;
    int t  = threadIdx.x;
    int to = t & 15, tm = t >> 4;

    float acc[4][8];
    #pragma unroll
    for(int i=0;i<4;i++)
        #pragma unroll
        for(int j=0;j<8;j++) acc[i][j]=0.f;

    for(int cc0=0; cc0<CC; cc0+=32){
        for(int idx=t; idx<32*128; idx+=256){
            int ci = idx>>7, m = idx&127;
            xs[ci*128 + m] = x[((size_t)(b*CC + cc0+ci))*HWN + m0 + m];
        }
        for(int idx=t; idx<64*32; idx+=256){
            int o = idx>>5, ci = idx&31;
            ws[o*33 + ci] = Wv[(size_t)(c0+o)*CC + cc0 + ci];
        }
        __syncthreads();
        #pragma unroll 8
        for(int ci=0;ci<32;ci++){
            float xv[8];
            #pragma unroll
            for(int j=0;j<8;j++) xv[j] = xs[ci*128 + tm*8 + j];
            #pragma unroll
            for(int i=0;i<4;i++){
                float wv = ws[(to+16*i)*33 + ci];
                #pragma unroll
                for(int j=0;j<8;j++) acc[i][j] = fmaf(wv, xv[j], acc[i][j]);
            }
        }
        __syncthreads();
    }
    // transposed store: [b][m][c]
    #pragma unroll
    for(int j=0;j<8;j++){
        int m = m0 + tm*8 + j;
        #pragma unroll
        for(int i=0;i<4;i++)
            g_Vt[((size_t)(b*HWN + m))*CC + c0 + to + 16*i] = acc[i][j];
    }
}

// ---------------- 5) 3-tap box smoothing ----------------
__global__ void k_smooth(){
    int idx = blockIdx.x*256 + threadIdx.x;
    int n = idx & (HWN-1);
    int k = (idx >> 12) & (KCN-1);
    int b = idx >> 17;
    size_t base = ((size_t)(b*KCN + k))*HWN + n;
    float a1 = g_b1r[base], a2 = g_b2r[base];
    if(n > 0)      { a1 += g_b1r[base-1]; a2 += g_b2r[base-1]; }
    if(n < HWN-1)  { a1 += g_b1r[base+1]; a2 += g_b2r[base+1]; }
    g_b1s[((size_t)(b*HWN + n))*KCN + k] = a1;
    g_b2s[base] = a2;
}

// ---------------- 6) fused attention: cp.async double-buffered, unsafe softmax ---
// smem: vs 2x[64][260] | ks 2x[32][64] | b2 2x[32][64] | ps [64][65] | qs[64][32] | b1t[64][32]
#define VS_OFF   0
#define KS_OFF   (2*64*260)
#define B2_OFF   (KS_OFF + 2*32*64)
#define PS_OFF   (B2_OFF + 2*32*64)
#define QS_OFF   (PS_OFF + 64*65)
#define B1_OFF   (QS_OFF + 64*32)
#define ATTN_SMEM ((B1_OFF + 64*32)*4)

__global__ void __launch_bounds__(256,1) k_attn(const float* __restrict__ wgb){
    extern __shared__ float sm[];
    float* vs  = sm + VS_OFF;
    float* ksb = sm + KS_OFF;
    float* b2b = sm + B2_OFF;
    float* ps  = sm + PS_OFF;
    float* qs  = sm + QS_OFF;
    float* b1t = sm + B1_OFF;
    const u32 smem_u32 = (u32)__cvta_generic_to_shared(sm);

    const int b  = blockIdx.y;
    const int n0 = blockIdx.x*64;
    const int t  = threadIdx.x;
    const int tr = t >> 4, tc = t & 15;
    const int r0 = tr*4;

    const float* vt_base = g_Vt  + (size_t)b*HWN*CC;
    const float* k_base  = g_K   + (size_t)b*KCN*HWN;
    const float* b2_base = g_b2s + (size_t)b*KCN*HWN;

    // ---- prefetch tile 0 into buffer 0 (V: 4096 chunks = full 64x256 tile) ----
    {
        const int m0g = 0;
        #pragma unroll
        for(int u=0;u<16;u++){
            int ch = t + u*256;              // 4096 chunks of 16B
            int row = ch>>6, c4 = (ch&63)*4; // 64 chunks (256 floats) per row
            cpa16(smem_u32 + (u32)((VS_OFF + row*260 + c4)*4),
                  vt_base + (size_t)(m0g+row)*CC + c4);
        }
        #pragma unroll
        for(int u=0;u<2;u++){
            int ch = t + u*256;              // 512 chunks (32 rows x 64 floats)
            int k = ch>>4, c4 = (ch&15)*4;
            cpa16(smem_u32 + (u32)((KS_OFF + k*64 + c4)*4),
                  k_base  + (size_t)k*HWN + m0g + c4);
            cpa16(smem_u32 + (u32)((B2_OFF + k*64 + c4)*4),
                  b2_base + (size_t)k*HWN + m0g + c4);
        }
        cpa_commit();
    }

    // ---- q / b1 for this row block ----
    for(int idx=t; idx<64*KCN; idx+=256){
        int r = idx>>5, k = idx&31;
        qs [idx] = g_Q  [((size_t)(b*HWN + n0 + r))*KCN + k];
        b1t[idx] = g_b1s[((size_t)(b*HWN + n0 + r))*KCN + k];
    }

    u64 acc[4][4][2];
    #pragma unroll
    for(int i=0;i<4;i++)
        #pragma unroll
        for(int jj=0;jj<4;jj++){ acc[i][jj][0]=0ULL; acc[i][jj][1]=0ULL; }
    float lsum[4] = {0.f, 0.f, 0.f, 0.f};

    const float cgb = wgb[0] * (1.0f/9.0f);

    for(int tile=0; tile<NT; tile++){
        const int cur = tile & 1;
        __syncthreads();   // prior PV reads of buf[1-cur] complete before overwrite

        if(tile+1 < NT){
            const int m0g = (tile+1)*64;
            const int bo  = (1-cur);
            #pragma unroll
            for(int u=0;u<16;u++){
                int ch = t + u*256;
                int row = ch>>6, c4 = (ch&63)*4;
                cpa16(smem_u32 + (u32)((VS_OFF + bo*64*260 + row*260 + c4)*4),
                      vt_base + (size_t)(m0g+row)*CC + c4);
            }
            #pragma unroll
            for(int u=0;u<2;u++){
                int ch = t + u*256;
                int k = ch>>4, c4 = (ch&15)*4;
                cpa16(smem_u32 + (u32)((KS_OFF + bo*32*64 + k*64 + c4)*4),
                      k_base  + (size_t)k*HWN + m0g + c4);
                cpa16(smem_u32 + (u32)((B2_OFF + bo*32*64 + k*64 + c4)*4),
                      b2_base + (size_t)k*HWN + m0g + c4);
            }
            cpa_commit();
            asm volatile("cp.async.wait_group 1;");   // current tile's group done
        } else {
            asm volatile("cp.async.wait_group 0;");
        }
        __syncthreads();   // copies visible block-wide

        const float* ksC = ksb + cur*32*64;
        const float* b2C = b2b + cur*32*64;
        const float* vsC = vs  + cur*64*260;

        // ---- logits: sim + pooled-bias (packed f32x2) ----
        u64 sim2[4][2], pool2[4][2];
        #pragma unroll
        for(int i=0;i<4;i++){ sim2[i][0]=sim2[i][1]=0ULL; pool2[i][0]=pool2[i][1]=0ULL; }
        #pragma unroll 8
        for(int k=0;k<KCN;k++){
            u64 kk0 = *(const u64*)&ksC[k*64 + tc*4];
            u64 kk1 = *(const u64*)&ksC[k*64 + tc*4 + 2];
            u64 bb0 = *(const u64*)&b2C[k*64 + tc*4];
            u64 bb1 = *(const u64*)&b2C[k*64 + tc*4 + 2];
            #pragma unroll
            for(int i=0;i<4;i++){
                u64 q2 = pack2same(qs [(r0+i)*32 + k]);
                u64 c2 = pack2same(b1t[(r0+i)*32 + k]);
                fma2(sim2[i][0],  q2, kk0);
                fma2(sim2[i][1],  q2, kk1);
                fma2(pool2[i][0], c2, bb0);
                fma2(pool2[i][1], c2, bb1);
            }
        }

        // ---- unsafe softmax: logits are bounded (|lg| << 80), no max tracking ----
        #pragma unroll
        for(int i=0;i<4;i++){
            float2 sa = unpack2(sim2[i][0]),  sb = unpack2(sim2[i][1]);
            float2 pa = unpack2(pool2[i][0]), pb = unpack2(pool2[i][1]);
            float e0 = __expf(sa.x * sigm(cgb*pa.x));
            float e1 = __expf(sa.y * sigm(cgb*pa.y));
            float e2 = __expf(sb.x * sigm(cgb*pb.x));
            float e3 = __expf(sb.y * sigm(cgb*pb.y));
            ps[(r0+i)*65 + tc*4 + 0] = e0;
            ps[(r0+i)*65 + tc*4 + 1] = e1;
            ps[(r0+i)*65 + tc*4 + 2] = e2;
            ps[(r0+i)*65 + tc*4 + 3] = e3;
            lsum[i] += (e0+e1) + (e2+e3);
        }
        __syncthreads();

        // ---- PV: acc += P @ V ----
        #pragma unroll 4
        for(int m=0;m<64;m++){
            u64 pp[4];
            #pragma unroll
            for(int i=0;i<4;i++) pp[i] = pack2same(ps[(r0+i)*65 + m]);
            #pragma unroll
            for(int jj=0;jj<4;jj++){
                const ulonglong2 v = *(const ulonglong2*)&vsC[m*260 + tc*4 + 64*jj];
                #pragma unroll
                for(int i=0;i<4;i++){
                    fma2(acc[i][jj][0], pp[i], v.x);
                    fma2(acc[i][jj][1], pp[i], v.y);
                }
            }
        }
    }

    // ---- reduce row sums across the 16-thread row group, normalize, write ----
    #pragma unroll
    for(int i=0;i<4;i++){
        float l = lsum[i];
        #pragma unroll
        for(int o=1;o<16;o<<=1) l += __shfl_xor_sync(0xffffffffu, l, o);
        float rl = __fdividef(1.0f, l);
        #pragma unroll
        for(int jj=0;jj<4;jj++){
            float2 a = unpack2(acc[i][jj][0]);
            float2 c = unpack2(acc[i][jj][1]);
            float4 o4; o4.x = a.x*rl; o4.y = a.y*rl; o4.z = c.x*rl; o4.w = c.y*rl;
            *(float4*)&g_ctx[((size_t)(b*HWN + n0 + r0 + i))*CC + tc*4 + 64*jj] = o4;
        }
    }
}

// ---------------- 7) output projection + BN + ReLU + residual ----------------
__global__ void __launch_bounds__(256) k_final(
    const float* __restrict__ x, const float* __restrict__ Wo,
    const float* __restrict__ bn_scale, const float* __restrict__ bn_bias,
    const float* __restrict__ bn_mean, const float* __restrict__ bn_var,
    const float* __restrict__ gamma, float* __restrict__ out)
{
    __shared__ float cs[128*33];
    __shared__ float ws[64*33];
    int b  = blockIdx.z;
    int c0 = blockIdx.y*64;
    int m0 = blockIdx.x*128;
    int t  = threadIdx.x;
    int to = t & 15, tm = t >> 4;

    float acc[4][8];
    #pragma unroll
    for(int i=0;i<4;i++)
        #pragma unroll
        for(int j=0;j<8;j++) acc[i][j]=0.f;

    for(int ci0=0; ci0<CC; ci0+=32){
        for(int idx=t; idx<128*32; idx+=256){
            int mm = idx>>5, cc = idx&31;
            cs[mm*33 + cc] = g_ctx[((size_t)(b*HWN + m0 + mm))*CC + ci0 + cc];
        }
        for(int idx=t; idx<64*32; idx+=256){
            int o = idx>>5, ci = idx&31;
            ws[o*33 + ci] = Wo[(size_t)(c0+o)*CC + ci0 + ci];
        }
        __syncthreads();
        #pragma unroll 8
        for(int ci=0;ci<32;ci++){
            float xv[8];
            #pragma unroll
            for(int j=0;j<8;j++) xv[j] = cs[(tm*8+j)*33 + ci];
            #pragma unroll
            for(int i=0;i<4;i++){
                float wv = ws[(to+16*i)*33 + ci];
                #pragma unroll
                for(int j=0;j<8;j++) acc[i][j] = fmaf(wv, xv[j], acc[i][j]);
            }
        }
        __syncthreads();
    }

    float gm = gamma[0];
    #pragma unroll
    for(int i=0;i<4;i++){
        int c = c0 + to + 16*i;
        float scl = bn_scale[c] * rsqrtf(bn_var[c] + EPSV);
        float mu  = bn_mean[c];
        float bi  = bn_bias[c];
        #pragma unroll
        for(int j=0;j<8;j++){
            size_t idx = ((size_t)(b*CC + c))*HWN + m0 + tm*8 + j;
            float y = (acc[i][j] - mu)*scl + bi;
            y = fmaxf(y, 0.f);
            out[idx] = gm*y + x[idx];
        }
    }
}

// ---------------- launch ----------------
extern "C" void kernel_launch(void* const* d_in, const int* in_sizes, int n_in,
                              void* d_out, int out_size){
    (void)in_sizes; (void)n_in; (void)out_size;
    const float* x        = (const float*)d_in[0];
    const float* Wq       = (const float*)d_in[1];
    const float* Wk       = (const float*)d_in[2];
    const float* Wv       = (const float*)d_in[3];
    const float* Wb1      = (const float*)d_in[4];
    const float* Wb2      = (const float*)d_in[5];
    const float* w_gb     = (const float*)d_in[6];
    const float* ge_w1    = (const float*)d_in[7];
    const float* ge_b1    = (const float*)d_in[8];
    const float* ge_w2    = (const float*)d_in[9];
    const float* ge_b2    = (const float*)d_in[10];
    const float* Wo       = (const float*)d_in[11];
    const float* bn_scale = (const float*)d_in[12];
    const float* bn_bias  = (const float*)d_in[13];
    const float* bn_mean  = (const float*)d_in[14];
    const float* bn_var   = (const float*)d_in[15];
    const float* gamma    = (const float*)d_in[16];
    float* out = (float*)d_out;

    cudaFuncSetAttribute(k_attn, cudaFuncAttributeMaxDynamicSharedMemorySize, ATTN_SMEM);

    k_mean    <<<dim3(CC/8, BB), 256>>>(x);
    k_gate    <<<BB, 256>>>(ge_w1, ge_b1, ge_w2, ge_b2);
    k_proj_qkb<<<dim3(HWN/128, BB), 256>>>(x, Wq, Wk, Wb1, Wb2);
    k_proj_v  <<<dim3(HWN/128, CC/64, BB), 256>>>(x, Wv);
    k_smooth  <<<(BB*KCN*HWN)/256, 256>>>();
    k_attn    <<<dim3(HWN/64, BB), 256, ATTN_SMEM>>>(w_gb);
    k_final   <<<dim3(HWN/128, CC/64, BB), 256>>>(x, Wo, bn_scale, bn_bias,
                                                  bn_mean, bn_var, gamma, out);
}

// round 7
// speedup vs baseline: 3.1941x; 2.0933x over previous
#include <cuda_runtime.h>
#include <cuda_bf16.h>
#include <math.h>

#define BB 2
#define CC 256
#define HWN 4096
#define KCN 32
#define RDN 16
#define EPSV 1e-5f

typedef unsigned long long u64;
typedef unsigned int u32;

// ---------------- scratch (device globals: allocation-free rule) ----------------
__device__ float g_mean[BB*CC];
__device__ float g_gate[BB*CC];
__device__ float g_Q   [BB*HWN*KCN];              // [b][m][k] fp32
__device__ __nv_bfloat16 g_Kb [BB*HWN*64];        // [b][m][hi0..31|lo0..31]
__device__ float g_b1r [BB*KCN*HWN];              // [b][k][m] fp32 pre-smooth
__device__ float g_b2r [BB*KCN*HWN];
__device__ float g_b1s [BB*HWN*KCN];              // [b][n][k] fp32 smoothed
__device__ __nv_bfloat16 g_b2b[BB*HWN*KCN];       // [b][m][k] bf16 smoothed
__device__ __nv_bfloat16 g_Vb [BB*CC*HWN];        // [b][c][m] bf16
__device__ float g_ctx [BB*HWN*CC];               // [b][n][c]

__device__ __forceinline__ float sigm(float x){
    return __fdividef(1.0f, 1.0f + __expf(-x));
}
__device__ __forceinline__ void cpa16(u32 dst, const void* src){
    asm volatile("cp.async.ca.shared.global [%0], [%1], 16;" :: "r"(dst), "l"(src));
}
__device__ __forceinline__ void cpa_commit(){ asm volatile("cp.async.commit_group;"); }

__device__ __forceinline__ u32 bf2(float lo, float hi){
    u32 r; asm("cvt.rn.bf16x2.f32 %0, %1, %2;" : "=r"(r) : "f"(hi), "f"(lo)); return r;
}

// m16n8k16 bf16 MMA, fp32 accum (baseline PTX, works on sm_100 non-'a')
__device__ __forceinline__ void mma16816(float* c, const u32* a, u32 b0, u32 b1){
    asm("mma.sync.aligned.m16n8k16.row.col.f32.bf16.bf16.f32 "
        "{%0,%1,%2,%3}, {%4,%5,%6,%7}, {%8,%9}, {%0,%1,%2,%3};"
        : "+f"(c[0]),"+f"(c[1]),"+f"(c[2]),"+f"(c[3])
        : "r"(a[0]),"r"(a[1]),"r"(a[2]),"r"(a[3]), "r"(b0),"r"(b1));
}

// ---------------- 1) per-(b,c) spatial mean ----------------
__global__ void k_mean(const float* __restrict__ x){
    int b = blockIdx.y;
    int c = blockIdx.x*8 + (threadIdx.x>>5);
    int lane = threadIdx.x & 31;
    const float* p = x + ((size_t)(b*CC + c))*HWN;
    float s = 0.f;
    for(int i=lane;i<HWN;i+=32) s += p[i];
    #pragma unroll
    for(int o=16;o;o>>=1) s += __shfl_xor_sync(0xffffffffu, s, o);
    if(lane==0) g_mean[b*CC+c] = s * (1.0f/HWN);
}

// ---------------- 2) GatherExcite MLP -> sigmoid gate ----------------
__global__ void k_gate(const float* __restrict__ w1, const float* __restrict__ b1,
                       const float* __restrict__ w2, const float* __restrict__ b2){
    __shared__ float sm[CC];
    __shared__ float sg[RDN];
    int b = blockIdx.x, t = threadIdx.x;
    sm[t] = g_mean[b*CC + t];
    __syncthreads();
    if(t < RDN){
        float a = b1[t];
        for(int c=0;c<CC;c++) a += w1[t*CC + c]*sm[c];
        sg[t] = fmaxf(a, 0.f);
    }
    __syncthreads();
    float a = b2[t];
    #pragma unroll
    for(int r=0;r<RDN;r++) a += w2[t*RDN + r]*sg[r];
    g_gate[b*CC + t] = sigm(a);
}

// ---------------- 3) q/k/b1/b2 projections ----------------
__global__ void __launch_bounds__(256) k_proj_qkb(
    const float* __restrict__ x,
    const float* __restrict__ Wq, const float* __restrict__ Wk,
    const float* __restrict__ Wb1, const float* __restrict__ Wb2)
{
    __shared__ float xs[32*128];
    __shared__ float ws[128*33];
    int b  = blockIdx.y;
    int m0 = blockIdx.x*128;
    int t  = threadIdx.x;
    int to = t & 15, tm = t >> 4;

    float acc[8][8];
    #pragma unroll
    for(int i=0;i<8;i++)
        #pragma unroll
        for(int j=0;j<8;j++) acc[i][j]=0.f;

    for(int cc0=0; cc0<CC; cc0+=32){
        for(int idx=t; idx<32*128; idx+=256){
            int ci = idx>>7, m = idx&127;
            xs[ci*128 + m] = x[((size_t)(b*CC + cc0+ci))*HWN + m0 + m];
        }
        for(int idx=t; idx<128*32; idx+=256){
            int o = idx>>5, ci = idx&31;
            int cg = cc0 + ci;
            float w;
            if(o<32)       w = Wq [(o   )*CC + cg];
            else if(o<64)  w = Wk [(o-32)*CC + cg] * g_gate[b*CC + cg];
            else if(o<96)  w = Wb1[(o-64)*CC + cg];
            else           w = Wb2[(o-96)*CC + cg];
            ws[o*33 + ci] = w;
        }
        __syncthreads();
        #pragma unroll 8
        for(int ci=0;ci<32;ci++){
            float xv[8];
            #pragma unroll
            for(int j=0;j<8;j++) xv[j] = xs[ci*128 + tm*8 + j];
            #pragma unroll
            for(int i=0;i<8;i++){
                float wv = ws[(to+16*i)*33 + ci];
                #pragma unroll
                for(int j=0;j<8;j++) acc[i][j] = fmaf(wv, xv[j], acc[i][j]);
            }
        }
        __syncthreads();
    }
    #pragma unroll
    for(int i=0;i<8;i++){
        int o = to + 16*i;
        #pragma unroll
        for(int j=0;j<8;j++){
            int m = m0 + tm*8 + j;
            float v = acc[i][j];
            if(o < 32)       g_Q  [((size_t)(b*HWN+m))*KCN + o] = v;
            else if(o < 64){
                __nv_bfloat16 h = __float2bfloat16(v);
                size_t base = ((size_t)(b*HWN+m))*64 + (o-32);
                g_Kb[base]      = h;
                g_Kb[base + 32] = __float2bfloat16(v - __bfloat162float(h));
            }
            else if(o < 96)  g_b1r[((size_t)(b*KCN + o-64))*HWN + m] = fmaxf(v, 0.f);
            else             g_b2r[((size_t)(b*KCN + o-96))*HWN + m] = fmaxf(v, 0.f);
        }
    }
}

// ---------------- 4) value projection -> g_Vb[b][c][m] bf16 ----------------
__global__ void __launch_bounds__(256) k_proj_v(
    const float* __restrict__ x, const float* __restrict__ Wv)
{
    __shared__ float xs[32*128];
    __shared__ float ws[64*33];
    int b  = blockIdx.z;
    int c0 = blockIdx.y*64;
    int m0 = blockIdx.x*128;
    int t  = threadIdx.x;
    int to = t & 15, tm = t >> 4;

    float acc[4][8];
    #pragma unroll
    for(int i=0;i<4;i++)
        #pragma unroll
        for(int j=0;j<8;j++) acc[i][j]=0.f;

    for(int cc0=0; cc0<CC; cc0+=32){
        for(int idx=t; idx<32*128; idx+=256){
            int ci = idx>>7, m = idx&127;
            xs[ci*128 + m] = x[((size_t)(b*CC + cc0+ci))*HWN + m0 + m];
        }
        for(int idx=t; idx<64*32; idx+=256){
            int o = idx>>5, ci = idx&31;
            ws[o*33 + ci] = Wv[(size_t)(c0+o)*CC + cc0 + ci];
        }
        __syncthreads();
        #pragma unroll 8
        for(int ci=0;ci<32;ci++){
            float xv[8];
            #pragma unroll
            for(int j=0;j<8;j++) xv[j] = xs[ci*128 + tm*8 + j];
            #pragma unroll
            for(int i=0;i<4;i++){
                float wv = ws[(to+16*i)*33 + ci];
                #pragma unroll
                for(int j=0;j<8;j++) acc[i][j] = fmaf(wv, xv[j], acc[i][j]);
            }
        }
        __syncthreads();
    }
    #pragma unroll
    for(int i=0;i<4;i++){
        int c = c0 + to + 16*i;
        #pragma unroll
        for(int j=0;j<8;j++)
            g_Vb[((size_t)(b*CC + c))*HWN + m0 + tm*8 + j] = __float2bfloat16(acc[i][j]);
    }
}

// ---------------- 5) 3-tap box smoothing ----------------
__global__ void k_smooth(){
    int idx = blockIdx.x*256 + threadIdx.x;
    int n = idx & (HWN-1);
    int k = (idx >> 12) & (KCN-1);
    int b = idx >> 17;
    size_t base = ((size_t)(b*KCN + k))*HWN + n;
    float a1 = g_b1r[base], a2 = g_b2r[base];
    if(n > 0)      { a1 += g_b1r[base-1]; a2 += g_b2r[base-1]; }
    if(n < HWN-1)  { a1 += g_b1r[base+1]; a2 += g_b2r[base+1]; }
    g_b1s[((size_t)(b*HWN + n))*KCN + k] = a1;
    g_b2b[((size_t)(b*HWN + n))*KCN + k] = __float2bfloat16(a2);
}

// ---------------- 6) fused attention on HMMA (mma.sync m16n8k16 bf16) ----------
// smem: V 2x[256 ch][72 bf16 pad] | K 2x[64 key][72 pad (hi32|lo32)] | B2 2x[64][40 pad]
#define VT_OFF   0
#define VT_SZ    36864
#define KT_OFF   (2*VT_SZ)            // 73728
#define KT_SZ    9216
#define B2_OFF   (KT_OFF + 2*KT_SZ)   // 92160
#define B2_SZ    5120
#define ATTN_SMEM (B2_OFF + 2*B2_SZ)  // 102400

__device__ __forceinline__ void attn_prefetch(u32 sb, int t, int b, int key0, int buf){
    #pragma unroll
    for(int u=0;u<16;u++){
        int ch = t + u*128;                 // 2048 chunks: 256 rows x 8
        int row = ch>>3, j = ch&7;
        cpa16(sb + VT_OFF + (u32)(buf*VT_SZ + row*144 + j*16),
              g_Vb + ((size_t)b*CC + row)*HWN + key0 + j*8);
    }
    #pragma unroll
    for(int u=0;u<4;u++){
        int ch = t + u*128;                 // 512 chunks: 64 rows x 8
        int key = ch>>3, j = ch&7;
        cpa16(sb + KT_OFF + (u32)(buf*KT_SZ + key*144 + j*16),
              g_Kb + ((size_t)(b*HWN) + key0 + key)*64 + j*8);
    }
    #pragma unroll
    for(int u=0;u<2;u++){
        int ch = t + u*128;                 // 256 chunks: 64 rows x 4
        int key = ch>>2, j = ch&3;
        cpa16(sb + B2_OFF + (u32)(buf*B2_SZ + key*80 + j*16),
              g_b2b + ((size_t)(b*HWN) + key0 + key)*KCN + j*8);
    }
}

__device__ __forceinline__ void splitpack(float2 f, u32 &hi, u32 &lo){
    float hx = __bfloat162float(__float2bfloat16(f.x));
    float hy = __bfloat162float(__float2bfloat16(f.y));
    hi = bf2(hx, hy);
    lo = bf2(f.x - hx, f.y - hy);
}

__global__ void __launch_bounds__(128,1) k_attn(const float* __restrict__ wgb){
    extern __shared__ char smr[];
    const u32 sb = (u32)__cvta_generic_to_shared(smr);
    const int t    = threadIdx.x;
    const int w    = t >> 5;
    const int lane = t & 31;
    const int g    = lane >> 2;     // row group / B-frag column
    const int tig  = lane & 3;
    const int b    = blockIdx.y;
    const int row0 = blockIdx.x*64 + w*16;

    attn_prefetch(sb, t, b, 0, 0);
    cpa_commit();

    // Q (hi/lo split) and B1 fragments, held in registers for the whole kernel
    u32 qhi[2][4], qlo[2][4], b1f[2][4];
    {
        const float* q0 = g_Q   + ((size_t)(b*HWN) + row0 + g)*KCN;
        const float* q8 = q0 + 8*KCN;
        const float* c0 = g_b1s + ((size_t)(b*HWN) + row0 + g)*KCN;
        const float* c8 = c0 + 8*KCN;
        #pragma unroll
        for(int ks=0;ks<2;ks++){
            #pragma unroll
            for(int h=0;h<2;h++){
                int col = 2*tig + 16*ks + 8*h;
                splitpack(*(const float2*)(q0+col), qhi[ks][2*h],   qlo[ks][2*h]);
                splitpack(*(const float2*)(q8+col), qhi[ks][2*h+1], qlo[ks][2*h+1]);
                float2 ga = *(const float2*)(c0+col);
                float2 gb = *(const float2*)(c8+col);
                b1f[ks][2*h]   = bf2(ga.x, ga.y);
                b1f[ks][2*h+1] = bf2(gb.x, gb.y);
            }
        }
    }

    float pv[32][4];
    #pragma unroll
    for(int i=0;i<32;i++){ pv[i][0]=0.f; pv[i][1]=0.f; pv[i][2]=0.f; pv[i][3]=0.f; }
    float ls0 = 0.f, ls1 = 0.f;
    const float cgb = wgb[0] * (1.0f/9.0f);

    for(int tile=0; tile<HWN/64; tile++){
        const int cur = tile & 1;
        __syncthreads();                       // everyone done reading buf[1-cur]
        if(tile+1 < HWN/64){
            attn_prefetch(sb, t, b, (tile+1)*64, 1-cur);
            cpa_commit();
            asm volatile("cp.async.wait_group 1;" ::: "memory");
        } else {
            asm volatile("cp.async.wait_group 0;" ::: "memory");
        }
        __syncthreads();

        const __nv_bfloat16* Ks  = (const __nv_bfloat16*)(smr + KT_OFF + cur*KT_SZ);
        const __nv_bfloat16* B2s = (const __nv_bfloat16*)(smr + B2_OFF + cur*B2_SZ);
        const __nv_bfloat16* Vs  = (const __nv_bfloat16*)(smr + VT_OFF + cur*VT_SZ);

        // ---- logits (hi/lo split sim + bf16 pool) + softmax + pack P ----
        u32 pa[8][2];
        #pragma unroll
        for(int nt=0; nt<8; nt++){
            float sa[4] = {0.f,0.f,0.f,0.f};
            float pl[4] = {0.f,0.f,0.f,0.f};
            const __nv_bfloat16* kr = Ks  + (nt*8 + g)*72;
            const __nv_bfloat16* br = B2s + (nt*8 + g)*40;
            #pragma unroll
            for(int ks=0;ks<2;ks++){
                u32 kh0 = *(const u32*)(kr + 16*ks + 2*tig);
                u32 kh1 = *(const u32*)(kr + 16*ks + 2*tig + 8);
                u32 kl0 = *(const u32*)(kr + 32 + 16*ks + 2*tig);
                u32 kl1 = *(const u32*)(kr + 32 + 16*ks + 2*tig + 8);
                u32 bb0 = *(const u32*)(br + 16*ks + 2*tig);
                u32 bb1 = *(const u32*)(br + 16*ks + 2*tig + 8);
                mma16816(sa, qhi[ks], kh0, kh1);
                mma16816(sa, qhi[ks], kl0, kl1);
                mma16816(sa, qlo[ks], kh0, kh1);
                mma16816(pl, b1f[ks], bb0, bb1);
            }
            float e0 = __expf(sa[0] * sigm(cgb*pl[0]));
            float e1 = __expf(sa[1] * sigm(cgb*pl[1]));
            float e2 = __expf(sa[2] * sigm(cgb*pl[2]));
            float e3 = __expf(sa[3] * sigm(cgb*pl[3]));
            ls0 += e0 + e1;
            ls1 += e2 + e3;
            pa[nt][0] = bf2(e0, e1);   // C-frag -> A-frag identity
            pa[nt][1] = bf2(e2, e3);
        }

        // ---- PV: acc += P @ V ----
        #pragma unroll
        for(int cnt=0; cnt<32; cnt++){
            const __nv_bfloat16* vr = Vs + (cnt*8 + g)*72;
            #pragma unroll
            for(int ks=0;ks<4;ks++){
                u32 v0 = *(const u32*)(vr + 16*ks + 2*tig);
                u32 v1 = *(const u32*)(vr + 16*ks + 2*tig + 8);
                u32 af[4] = { pa[2*ks][0], pa[2*ks][1], pa[2*ks+1][0], pa[2*ks+1][1] };
                mma16816(pv[cnt], af, v0, v1);
            }
        }
    }

    // ---- reduce exp-sums over the quad (lanes sharing a row), normalize, write ----
    #pragma unroll
    for(int o=1;o<4;o<<=1){
        ls0 += __shfl_xor_sync(0xffffffffu, ls0, o);
        ls1 += __shfl_xor_sync(0xffffffffu, ls1, o);
    }
    float rl0 = __fdividef(1.0f, ls0);
    float rl1 = __fdividef(1.0f, ls1);

    float* d0 = g_ctx + ((size_t)(b*HWN) + row0 + g    )*CC;
    float* d8 = g_ctx + ((size_t)(b*HWN) + row0 + g + 8)*CC;
    #pragma unroll
    for(int cnt=0; cnt<32; cnt++){
        float2 o0; o0.x = pv[cnt][0]*rl0; o0.y = pv[cnt][1]*rl0;
        float2 o1; o1.x = pv[cnt][2]*rl1; o1.y = pv[cnt][3]*rl1;
        *(float2*)(d0 + cnt*8 + 2*tig) = o0;
        *(float2*)(d8 + cnt*8 + 2*tig) = o1;
    }
}

// ---------------- 7) output projection + BN + ReLU + residual ----------------
__global__ void __launch_bounds__(256) k_final(
    const float* __restrict__ x, const float* __restrict__ Wo,
    const float* __restrict__ bn_scale, const float* __restrict__ bn_bias,
    const float* __restrict__ bn_mean, const float* __restrict__ bn_var,
    const float* __restrict__ gamma, float* __restrict__ out)
{
    __shared__ float cs[128*33];
    __shared__ float ws[64*33];
    int b  = blockIdx.z;
    int c0 = blockIdx.y*64;
    int m0 = blockIdx.x*128;
    int t  = threadIdx.x;
    int to = t & 15, tm = t >> 4;

    float acc[4][8];
    #pragma unroll
    for(int i=0;i<4;i++)
        #pragma unroll
        for(int j=0;j<8;j++) acc[i][j]=0.f;

    for(int ci0=0; ci0<CC; ci0+=32){
        for(int idx=t; idx<128*32; idx+=256){
            int mm = idx>>5, cc = idx&31;
            cs[mm*33 + cc] = g_ctx[((size_t)(b*HWN + m0 + mm))*CC + ci0 + cc];
        }
        for(int idx=t; idx<64*32; idx+=256){
            int o = idx>>5, ci = idx&31;
            ws[o*33 + ci] = Wo[(size_t)(c0+o)*CC + ci0 + ci];
        }
        __syncthreads();
        #pragma unroll 8
        for(int ci=0;ci<32;ci++){
            float xv[8];
            #pragma unroll
            for(int j=0;j<8;j++) xv[j] = cs[(tm*8+j)*33 + ci];
            #pragma unroll
            for(int i=0;i<4;i++){
                float wv = ws[(to+16*i)*33 + ci];
                #pragma unroll
                for(int j=0;j<8;j++) acc[i][j] = fmaf(wv, xv[j], acc[i][j]);
            }
        }
        __syncthreads();
    }

    float gm = gamma[0];
    #pragma unroll
    for(int i=0;i<4;i++){
        int c = c0 + to + 16*i;
        float scl = bn_scale[c] * rsqrtf(bn_var[c] + EPSV);
        float mu  = bn_mean[c];
        float bi  = bn_bias[c];
        #pragma unroll
        for(int j=0;j<8;j++){
            size_t idx = ((size_t)(b*CC + c))*HWN + m0 + tm*8 + j;
            float y = (acc[i][j] - mu)*scl + bi;
            y = fmaxf(y, 0.f);
            out[idx] = gm*y + x[idx];
        }
    }
}

// ---------------- launch ----------------
extern "C" void kernel_launch(void* const* d_in, const int* in_sizes, int n_in,
                              void* d_out, int out_size){
    (void)in_sizes; (void)n_in; (void)out_size;
    const float* x        = (const float*)d_in[0];
    const float* Wq       = (const float*)d_in[1];
    const float* Wk       = (const float*)d_in[2];
    const float* Wv       = (const float*)d_in[3];
    const float* Wb1      = (const float*)d_in[4];
    const float* Wb2      = (const float*)d_in[5];
    const float* w_gb     = (const float*)d_in[6];
    const float* ge_w1    = (const float*)d_in[7];
    const float* ge_b1    = (const float*)d_in[8];
    const float* ge_w2    = (const float*)d_in[9];
    const float* ge_b2    = (const float*)d_in[10];
    const float* Wo       = (const float*)d_in[11];
    const float* bn_scale = (const float*)d_in[12];
    const float* bn_bias  = (const float*)d_in[13];
    const float* bn_mean  = (const float*)d_in[14];
    const float* bn_var   = (const float*)d_in[15];
    const float* gamma    = (const float*)d_in[16];
    float* out = (float*)d_out;

    cudaFuncSetAttribute(k_attn, cudaFuncAttributeMaxDynamicSharedMemorySize, ATTN_SMEM);

    k_mean    <<<dim3(CC/8, BB), 256>>>(x);
    k_gate    <<<BB, 256>>>(ge_w1, ge_b1, ge_w2, ge_b2);
    k_proj_qkb<<<dim3(HWN/128, BB), 256>>>(x, Wq, Wk, Wb1, Wb2);
    k_proj_v  <<<dim3(HWN/128, CC/64, BB), 256>>>(x, Wv);
    k_smooth  <<<(BB*KCN*HWN)/256, 256>>>();
    k_attn    <<<dim3(HWN/64, BB), 128, ATTN_SMEM>>>(w_gb);
    k_final   <<<dim3(HWN/128, CC/64, BB), 256>>>(x, Wo, bn_scale, bn_bias,
                                                  bn_mean, bn_var, gamma, out);
}

// round 8
// speedup vs baseline: 6.2557x; 1.9585x over previous
#include <cuda_runtime.h>
#include <cuda_bf16.h>
#include <math.h>

#define BB 2
#define CC 256
#define HWN 4096
#define KCN 32
#define RDN 16
#define NO 384
#define EPSV 1e-5f

typedef unsigned long long u64;
typedef unsigned int u32;
typedef __nv_bfloat16 bf16;

// ---------------- scratch ----------------
__device__ float g_mean[BB*CC];
__device__ float g_gate[BB*CC];
__device__ bf16  g_xb  [BB*HWN*CC];     // [b][m][c]
__device__ bf16  g_Wb  [BB*NO*CC];      // [b][o][c]  (gate folded into K rows)
__device__ bf16  g_Wob [CC*CC];         // [o][c]
__device__ bf16  g_Qb  [BB*HWN*KCN];    // [b][m][k]
__device__ bf16  g_Kb  [BB*HWN*KCN];
__device__ float g_b1r [BB*HWN*KCN];    // [b][m][k] fp32 pre-smooth (relu'd)
__device__ float g_b2r [BB*HWN*KCN];
__device__ bf16  g_b1b [BB*HWN*KCN];    // smoothed
__device__ bf16  g_b2b [BB*HWN*KCN];
__device__ bf16  g_Vb  [BB*CC*HWN];     // [b][c][m]
__device__ bf16  g_ctxb[BB*HWN*CC];     // [b][n][c]

__device__ __forceinline__ float sigm(float x){
    return __fdividef(1.0f, 1.0f + __expf(-x));
}
__device__ __forceinline__ void cpa16(u32 dst, const void* src){
    asm volatile("cp.async.ca.shared.global [%0], [%1], 16;" :: "r"(dst), "l"(src));
}
__device__ __forceinline__ void cpa_commit(){ asm volatile("cp.async.commit_group;"); }
__device__ __forceinline__ u32 bf2(float lo, float hi){
    u32 r; asm("cvt.rn.bf16x2.f32 %0, %1, %2;" : "=r"(r) : "f"(hi), "f"(lo)); return r;
}
__device__ __forceinline__ void mma16816(float* c, const u32* a, u32 b0, u32 b1){
    asm("mma.sync.aligned.m16n8k16.row.col.f32.bf16.bf16.f32 "
        "{%0,%1,%2,%3}, {%4,%5,%6,%7}, {%8,%9}, {%0,%1,%2,%3};"
        : "+f"(c[0]),"+f"(c[1]),"+f"(c[2]),"+f"(c[3])
        : "r"(a[0]),"r"(a[1]),"r"(a[2]),"r"(a[3]), "r"(b0),"r"(b1));
}

// ---------------- 1) per-(b,c) spatial mean ----------------
__global__ void k_mean(const float* __restrict__ x){
    int b = blockIdx.y;
    int c = blockIdx.x*8 + (threadIdx.x>>5);
    int lane = threadIdx.x & 31;
    const float* p = x + ((size_t)(b*CC + c))*HWN;
    float s = 0.f;
    for(int i=lane;i<HWN;i+=32) s += p[i];
    #pragma unroll
    for(int o=16;o;o>>=1) s += __shfl_xor_sync(0xffffffffu, s, o);
    if(lane==0) g_mean[b*CC+c] = s * (1.0f/HWN);
}

// ---------------- 2) GatherExcite MLP -> sigmoid gate ----------------
__global__ void k_gate(const float* __restrict__ w1, const float* __restrict__ b1,
                       const float* __restrict__ w2, const float* __restrict__ b2){
    __shared__ float sm[CC];
    __shared__ float sg[RDN];
    int b = blockIdx.x, t = threadIdx.x;
    sm[t] = g_mean[b*CC + t];
    __syncthreads();
    if(t < RDN){
        float a = b1[t];
        for(int c=0;c<CC;c++) a += w1[t*CC + c]*sm[c];
        sg[t] = fmaxf(a, 0.f);
    }
    __syncthreads();
    float a = b2[t];
    #pragma unroll
    for(int r=0;r<RDN;r++) a += w2[t*RDN + r]*sg[r];
    g_gate[b*CC + t] = sigm(a);
}

// ---------------- 2b) x transpose+convert: [b][c][m] f32 -> [b][m][c] bf16 -------
__global__ void __launch_bounds__(128) k_xpose(const float* __restrict__ x){
    __shared__ float sm[32][129];
    int b = blockIdx.z, c0 = blockIdx.y*32, m0 = blockIdx.x*128;
    int t = threadIdx.x;
    #pragma unroll 4
    for(int ci=0; ci<32; ci++)
        sm[ci][t] = x[((size_t)(b*CC + c0 + ci))*HWN + m0 + t];
    __syncthreads();
    u32 pk[16];
    #pragma unroll
    for(int i=0;i<16;i++) pk[i] = bf2(sm[2*i][t], sm[2*i+1][t]);
    uint4* dst = (uint4*)(g_xb + ((size_t)(b*HWN) + m0 + t)*CC + c0);
    #pragma unroll
    for(int q=0;q<4;q++) dst[q] = ((uint4*)pk)[q];
}

// ---------------- 2c) weight prep: bf16 [o][c], gate folded ----------------
__global__ void k_wprep(const float* __restrict__ Wq, const float* __restrict__ Wk,
                        const float* __restrict__ Wb1, const float* __restrict__ Wb2,
                        const float* __restrict__ Wv, const float* __restrict__ Wo){
    int idx = blockIdx.x*256 + threadIdx.x;
    if(idx < BB*NO*CC){
        int c = idx & 255;
        int o = (idx >> 8) % NO;
        int b = idx / (NO*CC);
        float w;
        if(o < 32)       w = Wq [o*CC + c];
        else if(o < 64)  w = Wk [(o-32)*CC + c] * g_gate[b*CC + c];
        else if(o < 96)  w = Wb1[(o-64)*CC + c];
        else if(o < 128) w = Wb2[(o-96)*CC + c];
        else             w = Wv [(o-128)*CC + c];
        g_Wb[idx] = __float2bfloat16(w);
    } else {
        int j = idx - BB*NO*CC;   // CC*CC elems
        g_Wob[j] = __float2bfloat16(Wo[j]);
    }
}

// ---------------- 3) fused projections on HMMA ----------------
// smem: A 2x[128][72] bf16 (18432 ea) | B 2x[64][72] bf16 (9216 ea)
#define PJ_A_SZ  18432
#define PJ_B_OFF 36864
#define PJ_B_SZ  9216
#define PJ_SMEM  55296

__global__ void __launch_bounds__(128,1) k_projmm(){
    extern __shared__ char smr[];
    const u32 sb = (u32)__cvta_generic_to_shared(smr);
    const int t    = threadIdx.x;
    const int w    = t >> 5;
    const int lane = t & 31;
    const int g    = lane >> 2;
    const int tig  = lane & 3;
    const int b    = blockIdx.z;
    const int yblk = blockIdx.y;         // 0:{Q,K} 1:{b1,b2} 2..5:V
    const int m0   = blockIdx.x*128;
    const int o0   = yblk*64;

    const bf16* asrc = g_xb + ((size_t)(b*HWN) + m0)*CC;
    const bf16* bsrc = g_Wb + ((size_t)(b*NO)  + o0)*CC;

    float acc[2][8][4];
    #pragma unroll
    for(int mf=0;mf<2;mf++)
        #pragma unroll
        for(int bn=0;bn<8;bn++)
            #pragma unroll
            for(int q=0;q<4;q++) acc[mf][bn][q]=0.f;

    // prefetch chunk 0
    {
        #pragma unroll
        for(int u=0;u<8;u++){
            int ch = t + u*128;   // 1024: 128 rows x 8
            int row = ch>>3, j = ch&7;
            cpa16(sb + (u32)(row*144 + j*16), asrc + (size_t)row*CC + j*8);
        }
        #pragma unroll
        for(int u=0;u<4;u++){
            int ch = t + u*128;   // 512: 64 rows x 8
            int row = ch>>3, j = ch&7;
            cpa16(sb + PJ_B_OFF + (u32)(row*144 + j*16), bsrc + (size_t)row*CC + j*8);
        }
        cpa_commit();
    }

    for(int cc=0; cc<4; cc++){
        const int cur = cc & 1;
        __syncthreads();
        if(cc+1 < 4){
            const int nb = 1-cur;
            #pragma unroll
            for(int u=0;u<8;u++){
                int ch = t + u*128;
                int row = ch>>3, j = ch&7;
                cpa16(sb + (u32)(nb*PJ_A_SZ + row*144 + j*16),
                      asrc + (size_t)row*CC + (cc+1)*64 + j*8);
            }
            #pragma unroll
            for(int u=0;u<4;u++){
                int ch = t + u*128;
                int row = ch>>3, j = ch&7;
                cpa16(sb + (u32)(PJ_B_OFF + nb*PJ_B_SZ + row*144 + j*16),
                      bsrc + (size_t)row*CC + (cc+1)*64 + j*8);
            }
            cpa_commit();
            asm volatile("cp.async.wait_group 1;" ::: "memory");
        } else {
            asm volatile("cp.async.wait_group 0;" ::: "memory");
        }
        __syncthreads();

        const bf16* As = (const bf16*)(smr + cur*PJ_A_SZ);
        const bf16* Bs = (const bf16*)(smr + PJ_B_OFF + cur*PJ_B_SZ);
        #pragma unroll
        for(int ks=0;ks<4;ks++){
            u32 af[2][4];
            #pragma unroll
            for(int mf=0;mf<2;mf++){
                const bf16* ar = As + (w*32 + mf*16 + g)*72 + ks*16 + 2*tig;
                af[mf][0] = *(const u32*)ar;
                af[mf][1] = *(const u32*)(ar + 8*72);
                af[mf][2] = *(const u32*)(ar + 8);
                af[mf][3] = *(const u32*)(ar + 8*72 + 8);
            }
            #pragma unroll
            for(int bn=0;bn<8;bn++){
                const bf16* br = Bs + (bn*8 + g)*72 + ks*16 + 2*tig;
                u32 b0 = *(const u32*)br, b1 = *(const u32*)(br + 8);
                mma16816(acc[0][bn], af[0], b0, b1);
                mma16816(acc[1][bn], af[1], b0, b1);
            }
        }
    }

    if(yblk == 0){
        // cols 0-31 -> Qb[m][k], 32-63 -> Kb[m][k]  (bf16x2 direct)
        #pragma unroll
        for(int mf=0;mf<2;mf++){
            int r0g = m0 + w*32 + mf*16 + g;
            #pragma unroll
            for(int bn=0;bn<8;bn++){
                int o = bn*8 + 2*tig;
                bf16* base = (o<32) ? g_Qb : g_Kb;
                int oo = o & 31;
                *(u32*)(base + ((size_t)(b*HWN) + r0g    )*KCN + oo) = bf2(acc[mf][bn][0], acc[mf][bn][1]);
                *(u32*)(base + ((size_t)(b*HWN) + r0g + 8)*KCN + oo) = bf2(acc[mf][bn][2], acc[mf][bn][3]);
            }
        }
    } else if(yblk == 1){
        // cols 0-31 -> b1r, 32-63 -> b2r (relu, fp32)
        #pragma unroll
        for(int mf=0;mf<2;mf++){
            int r0g = m0 + w*32 + mf*16 + g;
            #pragma unroll
            for(int bn=0;bn<8;bn++){
                int o = bn*8 + 2*tig;
                float* base = (o<32) ? g_b1r : g_b2r;
                int oo = o & 31;
                float2 v0; v0.x = fmaxf(acc[mf][bn][0],0.f); v0.y = fmaxf(acc[mf][bn][1],0.f);
                float2 v1; v1.x = fmaxf(acc[mf][bn][2],0.f); v1.y = fmaxf(acc[mf][bn][3],0.f);
                *(float2*)(base + ((size_t)(b*HWN) + r0g    )*KCN + oo) = v0;
                *(float2*)(base + ((size_t)(b*HWN) + r0g + 8)*KCN + oo) = v1;
            }
        }
    } else {
        // V: transpose epilogue -> g_Vb[b][c][m] bf16
        __syncthreads();
        float* smf = (float*)smr;         // [64][132]
        #pragma unroll
        for(int mf=0;mf<2;mf++){
            int rl = w*32 + mf*16 + g;
            #pragma unroll
            for(int bn=0;bn<8;bn++){
                int col = bn*8 + 2*tig;
                smf[col*132 + rl]         = acc[mf][bn][0];
                smf[(col+1)*132 + rl]     = acc[mf][bn][1];
                smf[col*132 + rl + 8]     = acc[mf][bn][2];
                smf[(col+1)*132 + rl + 8] = acc[mf][bn][3];
            }
        }
        __syncthreads();
        int cc = t >> 1, half = t & 1;
        int c = (yblk-2)*64 + cc;
        bf16* dst = g_Vb + ((size_t)(b*CC) + c)*HWN + m0 + half*64;
        u32 pk[32];
        #pragma unroll
        for(int j=0;j<32;j++)
            pk[j] = bf2(smf[cc*132 + half*64 + 2*j], smf[cc*132 + half*64 + 2*j + 1]);
        #pragma unroll
        for(int q=0;q<8;q++) ((uint4*)dst)[q] = ((uint4*)pk)[q];
    }
}

// ---------------- 5) 3-tap box smoothing ([m][k] layout) ----------------
__global__ void k_smooth(){
    int idx = blockIdx.x*256 + threadIdx.x;
    int k = idx & 31;
    int m = (idx >> 5) & (HWN-1);
    int b = idx >> 17;
    size_t base = ((size_t)(b*HWN) + m)*KCN + k;
    float a1 = g_b1r[base], a2 = g_b2r[base];
    if(m > 0)      { a1 += g_b1r[base-KCN]; a2 += g_b2r[base-KCN]; }
    if(m < HWN-1)  { a1 += g_b1r[base+KCN]; a2 += g_b2r[base+KCN]; }
    g_b1b[base] = __float2bfloat16(a1);
    g_b2b[base] = __float2bfloat16(a2);
}

// ---------------- 6) fused attention on HMMA (single-bf16 logits) ----------
// smem: V 2x[256][72 bf16] | K 2x[64][40 bf16] | B2 2x[64][40 bf16]
#define VT_SZ    36864
#define KT_OFF   73728
#define KT_SZ    5120
#define B2_OFF   83968
#define B2_SZ    5120
#define ATTN_SMEM 94208

__device__ __forceinline__ void attn_prefetch(u32 sb, int t, int b, int key0, int buf){
    #pragma unroll
    for(int u=0;u<16;u++){
        int ch = t + u*128;                 // 2048: 256 rows x 8
        int row = ch>>3, j = ch&7;
        cpa16(sb + (u32)(buf*VT_SZ + row*144 + j*16),
              g_Vb + ((size_t)b*CC + row)*HWN + key0 + j*8);
    }
    #pragma unroll
    for(int u=0;u<2;u++){
        int ch = t + u*128;                 // 256: 64 rows x 4
        int key = ch>>2, j = ch&3;
        cpa16(sb + (u32)(KT_OFF + buf*KT_SZ + key*80 + j*16),
              g_Kb + ((size_t)(b*HWN) + key0 + key)*KCN + j*8);
        cpa16(sb + (u32)(B2_OFF + buf*B2_SZ + key*80 + j*16),
              g_b2b + ((size_t)(b*HWN) + key0 + key)*KCN + j*8);
    }
}

__global__ void __launch_bounds__(128,1) k_attn(const float* __restrict__ wgb){
    extern __shared__ char smr[];
    const u32 sb = (u32)__cvta_generic_to_shared(smr);
    const int t    = threadIdx.x;
    const int w    = t >> 5;
    const int lane = t & 31;
    const int g    = lane >> 2;
    const int tig  = lane & 3;
    const int b    = blockIdx.y;
    const int row0 = blockIdx.x*64 + w*16;

    attn_prefetch(sb, t, b, 0, 0);
    cpa_commit();

    // Q / B1 fragments (bf16 direct)
    u32 qf[2][4], b1f[2][4];
    {
        const bf16* q0 = g_Qb  + ((size_t)(b*HWN) + row0 + g)*KCN;
        const bf16* c0 = g_b1b + ((size_t)(b*HWN) + row0 + g)*KCN;
        #pragma unroll
        for(int ks=0;ks<2;ks++){
            qf[ks][0]  = *(const u32*)(q0 + ks*16 + 2*tig);
            qf[ks][1]  = *(const u32*)(q0 + 8*KCN + ks*16 + 2*tig);
            qf[ks][2]  = *(const u32*)(q0 + ks*16 + 2*tig + 8);
            qf[ks][3]  = *(const u32*)(q0 + 8*KCN + ks*16 + 2*tig + 8);
            b1f[ks][0] = *(const u32*)(c0 + ks*16 + 2*tig);
            b1f[ks][1] = *(const u32*)(c0 + 8*KCN + ks*16 + 2*tig);
            b1f[ks][2] = *(const u32*)(c0 + ks*16 + 2*tig + 8);
            b1f[ks][3] = *(const u32*)(c0 + 8*KCN + ks*16 + 2*tig + 8);
        }
    }

    float pv[32][4];
    #pragma unroll
    for(int i=0;i<32;i++){ pv[i][0]=0.f; pv[i][1]=0.f; pv[i][2]=0.f; pv[i][3]=0.f; }
    float ls0 = 0.f, ls1 = 0.f;
    const float cgb = wgb[0] * (1.0f/9.0f);

    for(int tile=0; tile<HWN/64; tile++){
        const int cur = tile & 1;
        __syncthreads();
        if(tile+1 < HWN/64){
            attn_prefetch(sb, t, b, (tile+1)*64, 1-cur);
            cpa_commit();
            asm volatile("cp.async.wait_group 1;" ::: "memory");
        } else {
            asm volatile("cp.async.wait_group 0;" ::: "memory");
        }
        __syncthreads();

        const bf16* Ks  = (const bf16*)(smr + KT_OFF + cur*KT_SZ);
        const bf16* B2s = (const bf16*)(smr + B2_OFF + cur*B2_SZ);
        const bf16* Vs  = (const bf16*)(smr + cur*VT_SZ);

        u32 pa[8][2];
        #pragma unroll
        for(int nt=0; nt<8; nt++){
            float sa[4] = {0.f,0.f,0.f,0.f};
            float pl[4] = {0.f,0.f,0.f,0.f};
            const bf16* kr = Ks  + (nt*8 + g)*40;
            const bf16* br = B2s + (nt*8 + g)*40;
            #pragma unroll
            for(int ks=0;ks<2;ks++){
                u32 k0  = *(const u32*)(kr + ks*16 + 2*tig);
                u32 k1  = *(const u32*)(kr + ks*16 + 2*tig + 8);
                u32 bb0 = *(const u32*)(br + ks*16 + 2*tig);
                u32 bb1 = *(const u32*)(br + ks*16 + 2*tig + 8);
                mma16816(sa, qf[ks],  k0,  k1);
                mma16816(pl, b1f[ks], bb0, bb1);
            }
            float e0 = __expf(sa[0] * sigm(cgb*pl[0]));
            float e1 = __expf(sa[1] * sigm(cgb*pl[1]));
            float e2 = __expf(sa[2] * sigm(cgb*pl[2]));
            float e3 = __expf(sa[3] * sigm(cgb*pl[3]));
            ls0 += e0 + e1;
            ls1 += e2 + e3;
            pa[nt][0] = bf2(e0, e1);
            pa[nt][1] = bf2(e2, e3);
        }

        #pragma unroll
        for(int cnt=0; cnt<32; cnt++){
            const bf16* vr = Vs + (cnt*8 + g)*72;
            #pragma unroll
            for(int ks=0;ks<4;ks++){
                u32 v0 = *(const u32*)(vr + 16*ks + 2*tig);
                u32 v1 = *(const u32*)(vr + 16*ks + 2*tig + 8);
                u32 af[4] = { pa[2*ks][0], pa[2*ks][1], pa[2*ks+1][0], pa[2*ks+1][1] };
                mma16816(pv[cnt], af, v0, v1);
            }
        }
    }

    #pragma unroll
    for(int o=1;o<4;o<<=1){
        ls0 += __shfl_xor_sync(0xffffffffu, ls0, o);
        ls1 += __shfl_xor_sync(0xffffffffu, ls1, o);
    }
    float rl0 = __fdividef(1.0f, ls0);
    float rl1 = __fdividef(1.0f, ls1);

    u32* d0 = (u32*)(g_ctxb + ((size_t)(b*HWN) + row0 + g    )*CC);
    u32* d8 = (u32*)(g_ctxb + ((size_t)(b*HWN) + row0 + g + 8)*CC);
    #pragma unroll
    for(int cnt=0; cnt<32; cnt++){
        d0[cnt*4 + tig] = bf2(pv[cnt][0]*rl0, pv[cnt][1]*rl0);
        d8[cnt*4 + tig] = bf2(pv[cnt][2]*rl1, pv[cnt][3]*rl1);
    }
}

// ---------------- 7) output projection (HMMA) + BN + ReLU + residual ----------
__global__ void __launch_bounds__(128,1) k_final(
    const float* __restrict__ x,
    const float* __restrict__ bn_scale, const float* __restrict__ bn_bias,
    const float* __restrict__ bn_mean, const float* __restrict__ bn_var,
    const float* __restrict__ gamma, float* __restrict__ out)
{
    extern __shared__ char smr[];
    const u32 sb = (u32)__cvta_generic_to_shared(smr);
    const int t    = threadIdx.x;
    const int w    = t >> 5;
    const int lane = t & 31;
    const int g    = lane >> 2;
    const int tig  = lane & 3;
    const int b    = blockIdx.z;
    const int c0   = blockIdx.y*64;
    const int m0   = blockIdx.x*128;

    const bf16* asrc = g_ctxb + ((size_t)(b*HWN) + m0)*CC;
    const bf16* bsrc = g_Wob + (size_t)c0*CC;

    float acc[2][8][4];
    #pragma unroll
    for(int mf=0;mf<2;mf++)
        #pragma unroll
        for(int bn=0;bn<8;bn++)
            #pragma unroll
            for(int q=0;q<4;q++) acc[mf][bn][q]=0.f;

    {
        #pragma unroll
        for(int u=0;u<8;u++){
            int ch = t + u*128;
            int row = ch>>3, j = ch&7;
            cpa16(sb + (u32)(row*144 + j*16), asrc + (size_t)row*CC + j*8);
        }
        #pragma unroll
        for(int u=0;u<4;u++){
            int ch = t + u*128;
            int row = ch>>3, j = ch&7;
            cpa16(sb + PJ_B_OFF + (u32)(row*144 + j*16), bsrc + (size_t)row*CC + j*8);
        }
        cpa_commit();
    }

    for(int cc=0; cc<4; cc++){
        const int cur = cc & 1;
        __syncthreads();
        if(cc+1 < 4){
            const int nb = 1-cur;
            #pragma unroll
            for(int u=0;u<8;u++){
                int ch = t + u*128;
                int row = ch>>3, j = ch&7;
                cpa16(sb + (u32)(nb*PJ_A_SZ + row*144 + j*16),
                      asrc + (size_t)row*CC + (cc+1)*64 + j*8);
            }
            #pragma unroll
            for(int u=0;u<4;u++){
                int ch = t + u*128;
                int row = ch>>3, j = ch&7;
                cpa16(sb + (u32)(PJ_B_OFF + nb*PJ_B_SZ + row*144 + j*16),
                      bsrc + (size_t)row*CC + (cc+1)*64 + j*8);
            }
            cpa_commit();
            asm volatile("cp.async.wait_group 1;" ::: "memory");
        } else {
            asm volatile("cp.async.wait_group 0;" ::: "memory");
        }
        __syncthreads();

        const bf16* As = (const bf16*)(smr + cur*PJ_A_SZ);
        const bf16* Bs = (const bf16*)(smr + PJ_B_OFF + cur*PJ_B_SZ);
        #pragma unroll
        for(int ks=0;ks<4;ks++){
            u32 af[2][4];
            #pragma unroll
            for(int mf=0;mf<2;mf++){
                const bf16* ar = As + (w*32 + mf*16 + g)*72 + ks*16 + 2*tig;
                af[mf][0] = *(const u32*)ar;
                af[mf][1] = *(const u32*)(ar + 8*72);
                af[mf][2] = *(const u32*)(ar + 8);
                af[mf][3] = *(const u32*)(ar + 8*72 + 8);
            }
            #pragma unroll
            for(int bn=0;bn<8;bn++){
                const bf16* br = Bs + (bn*8 + g)*72 + ks*16 + 2*tig;
                u32 b0 = *(const u32*)br, b1 = *(const u32*)(br + 8);
                mma16816(acc[0][bn], af[0], b0, b1);
                mma16816(acc[1][bn], af[1], b0, b1);
            }
        }
    }

    // transpose epilogue via smem, then BN + relu + residual, coalesced out[c][m]
    __syncthreads();
    float* smf = (float*)smr;   // [64][132]
    #pragma unroll
    for(int mf=0;mf<2;mf++){
        int rl = w*32 + mf*16 + g;
        #pragma unroll
        for(int bn=0;bn<8;bn++){
            int col = bn*8 + 2*tig;
            smf[col*132 + rl]         = acc[mf][bn][0];
            smf[(col+1)*132 + rl]     = acc[mf][bn][1];
            smf[col*132 + rl + 8]     = acc[mf][bn][2];
            smf[(col+1)*132 + rl + 8] = acc[mf][bn][3];
        }
    }
    __syncthreads();
    {
        int cc = t >> 1, half = t & 1;
        int c = c0 + cc;
        float scl = bn_scale[c] * rsqrtf(bn_var[c] + EPSV);
        float mu  = bn_mean[c];
        float bi  = bn_bias[c];
        float gm  = gamma[0];
        const float* xr = x   + ((size_t)(b*CC) + c)*HWN + m0 + half*64;
        float* orow     = out + ((size_t)(b*CC) + c)*HWN + m0 + half*64;
        #pragma unroll
        for(int q=0;q<16;q++){
            float4 xv = *(const float4*)(xr + q*4);
            float4 o;
            float v0 = smf[cc*132 + half*64 + q*4 + 0];
            float v1 = smf[cc*132 + half*64 + q*4 + 1];
            float v2 = smf[cc*132 + half*64 + q*4 + 2];
            float v3 = smf[cc*132 + half*64 + q*4 + 3];
            o.x = gm*fmaxf((v0-mu)*scl+bi, 0.f) + xv.x;
            o.y = gm*fmaxf((v1-mu)*scl+bi, 0.f) + xv.y;
            o.z = gm*fmaxf((v2-mu)*scl+bi, 0.f) + xv.z;
            o.w = gm*fmaxf((v3-mu)*scl+bi, 0.f) + xv.w;
            *(float4*)(orow + q*4) = o;
        }
    }
}

// ---------------- launch ----------------
extern "C" void kernel_launch(void* const* d_in, const int* in_sizes, int n_in,
                              void* d_out, int out_size){
    (void)in_sizes; (void)n_in; (void)out_size;
    const float* x        = (const float*)d_in[0];
    const float* Wq       = (const float*)d_in[1];
    const float* Wk       = (const float*)d_in[2];
    const float* Wv       = (const float*)d_in[3];
    const float* Wb1      = (const float*)d_in[4];
    const float* Wb2      = (const float*)d_in[5];
    const float* w_gb     = (const float*)d_in[6];
    const float* ge_w1    = (const float*)d_in[7];
    const float* ge_b1    = (const float*)d_in[8];
    const float* ge_w2    = (const float*)d_in[9];
    const float* ge_b2    = (const float*)d_in[10];
    const float* Wo       = (const float*)d_in[11];
    const float* bn_scale = (const float*)d_in[12];
    const float* bn_bias  = (const float*)d_in[13];
    const float* bn_mean  = (const float*)d_in[14];
    const float* bn_var   = (const float*)d_in[15];
    const float* gamma    = (const float*)d_in[16];
    float* out = (float*)d_out;

    cudaFuncSetAttribute(k_attn,   cudaFuncAttributeMaxDynamicSharedMemorySize, ATTN_SMEM);
    cudaFuncSetAttribute(k_projmm, cudaFuncAttributeMaxDynamicSharedMemorySize, PJ_SMEM);
    cudaFuncSetAttribute(k_final,  cudaFuncAttributeMaxDynamicSharedMemorySize, PJ_SMEM);

    k_mean  <<<dim3(CC/8, BB), 256>>>(x);
    k_gate  <<<BB, 256>>>(ge_w1, ge_b1, ge_w2, ge_b2);
    k_xpose <<<dim3(HWN/128, CC/32, BB), 128>>>(x);
    k_wprep <<<(BB*NO*CC + CC*CC)/256, 256>>>(Wq, Wk, Wb1, Wb2, Wv, Wo);
    k_projmm<<<dim3(HWN/128, NO/64, BB), 128, PJ_SMEM>>>();
    k_smooth<<<(BB*HWN*KCN)/256, 256>>>();
    k_attn  <<<dim3(HWN/64, BB), 128, ATTN_SMEM>>>(w_gb);
    k_final <<<dim3(HWN/128, CC/64, BB), 128, PJ_SMEM>>>(x, bn_scale, bn_bias,
                                                         bn_mean, bn_var, gamma, out);
}

// round 9
// speedup vs baseline: 7.7092x; 1.2323x over previous
#include <cuda_runtime.h>
#include <cuda_bf16.h>
#include <math.h>

#define BB 2
#define CC 256
#define HWN 4096
#define KCN 32
#define RDN 16
#define NO 384
#define EPSV 1e-5f

typedef unsigned long long u64;
typedef unsigned int u32;
typedef __nv_bfloat16 bf16;

// ---------------- scratch ----------------
__device__ float g_mean[BB*CC];
__device__ float g_gate[BB*CC];
__device__ bf16  g_xb  [BB*HWN*CC];     // [b][m][c]
__device__ bf16  g_Wb  [BB*NO*CC];      // [b][o][c]  (gate folded into K rows)
__device__ bf16  g_Wob [CC*CC];         // [o][c]
__device__ bf16  g_Qb  [BB*HWN*KCN];    // [b][m][k]
__device__ bf16  g_Kb  [BB*HWN*KCN];
__device__ float g_b1r [BB*HWN*KCN];    // [b][m][k] fp32 pre-smooth (relu'd)
__device__ float g_b2r [BB*HWN*KCN];
__device__ bf16  g_b1b [BB*HWN*KCN];    // smoothed
__device__ bf16  g_b2b [BB*HWN*KCN];
__device__ bf16  g_Vb  [BB*CC*HWN];     // [b][c][m]
__device__ bf16  g_ctxb[BB*HWN*CC];     // [b][n][c]

__device__ __forceinline__ float sigm(float x){
    return __fdividef(1.0f, 1.0f + __expf(-x));
}
__device__ __forceinline__ void cpa16(u32 dst, const void* src){
    asm volatile("cp.async.ca.shared.global [%0], [%1], 16;" :: "r"(dst), "l"(src));
}
__device__ __forceinline__ void cpa_commit(){ asm volatile("cp.async.commit_group;"); }
__device__ __forceinline__ u32 bf2(float lo, float hi){
    u32 r; asm("cvt.rn.bf16x2.f32 %0, %1, %2;" : "=r"(r) : "f"(hi), "f"(lo)); return r;
}
__device__ __forceinline__ void mma16816(float* c, const u32* a, u32 b0, u32 b1){
    asm("mma.sync.aligned.m16n8k16.row.col.f32.bf16.bf16.f32 "
        "{%0,%1,%2,%3}, {%4,%5,%6,%7}, {%8,%9}, {%0,%1,%2,%3};"
        : "+f"(c[0]),"+f"(c[1]),"+f"(c[2]),"+f"(c[3])
        : "r"(a[0]),"r"(a[1]),"r"(a[2]),"r"(a[3]), "r"(b0),"r"(b1));
}

// ---------------- 1) per-(b,c) spatial mean ----------------
__global__ void k_mean(const float* __restrict__ x){
    int b = blockIdx.y;
    int c = blockIdx.x*8 + (threadIdx.x>>5);
    int lane = threadIdx.x & 31;
    const float* p = x + ((size_t)(b*CC + c))*HWN;
    float s = 0.f;
    for(int i=lane;i<HWN;i+=32) s += p[i];
    #pragma unroll
    for(int o=16;o;o>>=1) s += __shfl_xor_sync(0xffffffffu, s, o);
    if(lane==0) g_mean[b*CC+c] = s * (1.0f/HWN);
}

// ---------------- 2) GatherExcite MLP -> sigmoid gate ----------------
__global__ void k_gate(const float* __restrict__ w1, const float* __restrict__ b1,
                       const float* __restrict__ w2, const float* __restrict__ b2){
    __shared__ float sm[CC];
    __shared__ float sg[RDN];
    int b = blockIdx.x, t = threadIdx.x;
    sm[t] = g_mean[b*CC + t];
    __syncthreads();
    if(t < RDN){
        float a = b1[t];
        for(int c=0;c<CC;c++) a += w1[t*CC + c]*sm[c];
        sg[t] = fmaxf(a, 0.f);
    }
    __syncthreads();
    float a = b2[t];
    #pragma unroll
    for(int r=0;r<RDN;r++) a += w2[t*RDN + r]*sg[r];
    g_gate[b*CC + t] = sigm(a);
}

// ---------------- 2b) x transpose+convert: [b][c][m] f32 -> [b][m][c] bf16 -------
__global__ void __launch_bounds__(128) k_xpose(const float* __restrict__ x){
    __shared__ float sm[32][129];
    int b = blockIdx.z, c0 = blockIdx.y*32, m0 = blockIdx.x*128;
    int t = threadIdx.x;
    #pragma unroll 4
    for(int ci=0; ci<32; ci++)
        sm[ci][t] = x[((size_t)(b*CC + c0 + ci))*HWN + m0 + t];
    __syncthreads();
    u32 pk[16];
    #pragma unroll
    for(int i=0;i<16;i++) pk[i] = bf2(sm[2*i][t], sm[2*i+1][t]);
    uint4* dst = (uint4*)(g_xb + ((size_t)(b*HWN) + m0 + t)*CC + c0);
    #pragma unroll
    for(int q=0;q<4;q++) dst[q] = ((uint4*)pk)[q];
}

// ---------------- 2c) weight prep: bf16 [o][c], gate folded ----------------
__global__ void k_wprep(const float* __restrict__ Wq, const float* __restrict__ Wk,
                        const float* __restrict__ Wb1, const float* __restrict__ Wb2,
                        const float* __restrict__ Wv, const float* __restrict__ Wo){
    int idx = blockIdx.x*256 + threadIdx.x;
    if(idx < BB*NO*CC){
        int c = idx & 255;
        int o = (idx >> 8) % NO;
        int b = idx / (NO*CC);
        float w;
        if(o < 32)       w = Wq [o*CC + c];
        else if(o < 64)  w = Wk [(o-32)*CC + c] * g_gate[b*CC + c];
        else if(o < 96)  w = Wb1[(o-64)*CC + c];
        else if(o < 128) w = Wb2[(o-96)*CC + c];
        else             w = Wv [(o-128)*CC + c];
        g_Wb[idx] = __float2bfloat16(w);
    } else {
        int j = idx - BB*NO*CC;   // CC*CC elems
        g_Wob[j] = __float2bfloat16(Wo[j]);
    }
}

// ---------------- 3) fused projections on HMMA ----------------
// smem: A 2x[128][72] bf16 (18432 ea) | B 2x[64][72] bf16 (9216 ea)
#define PJ_A_SZ  18432
#define PJ_B_OFF 36864
#define PJ_B_SZ  9216
#define PJ_SMEM  55296

__global__ void __launch_bounds__(128,1) k_projmm(){
    extern __shared__ char smr[];
    const u32 sb = (u32)__cvta_generic_to_shared(smr);
    const int t    = threadIdx.x;
    const int w    = t >> 5;
    const int lane = t & 31;
    const int g    = lane >> 2;
    const int tig  = lane & 3;
    const int b    = blockIdx.z;
    const int yblk = blockIdx.y;         // 0:{Q,K} 1:{b1,b2} 2..5:V
    const int m0   = blockIdx.x*128;
    const int o0   = yblk*64;

    const bf16* asrc = g_xb + ((size_t)(b*HWN) + m0)*CC;
    const bf16* bsrc = g_Wb + ((size_t)(b*NO)  + o0)*CC;

    float acc[2][8][4];
    #pragma unroll
    for(int mf=0;mf<2;mf++)
        #pragma unroll
        for(int bn=0;bn<8;bn++)
            #pragma unroll
            for(int q=0;q<4;q++) acc[mf][bn][q]=0.f;

    {
        #pragma unroll
        for(int u=0;u<8;u++){
            int ch = t + u*128;
            int row = ch>>3, j = ch&7;
            cpa16(sb + (u32)(row*144 + j*16), asrc + (size_t)row*CC + j*8);
        }
        #pragma unroll
        for(int u=0;u<4;u++){
            int ch = t + u*128;
            int row = ch>>3, j = ch&7;
            cpa16(sb + PJ_B_OFF + (u32)(row*144 + j*16), bsrc + (size_t)row*CC + j*8);
        }
        cpa_commit();
    }

    for(int cc=0; cc<4; cc++){
        const int cur = cc & 1;
        __syncthreads();
        if(cc+1 < 4){
            const int nb = 1-cur;
            #pragma unroll
            for(int u=0;u<8;u++){
                int ch = t + u*128;
                int row = ch>>3, j = ch&7;
                cpa16(sb + (u32)(nb*PJ_A_SZ + row*144 + j*16),
                      asrc + (size_t)row*CC + (cc+1)*64 + j*8);
            }
            #pragma unroll
            for(int u=0;u<4;u++){
                int ch = t + u*128;
                int row = ch>>3, j = ch&7;
                cpa16(sb + (u32)(PJ_B_OFF + nb*PJ_B_SZ + row*144 + j*16),
                      bsrc + (size_t)row*CC + (cc+1)*64 + j*8);
            }
            cpa_commit();
            asm volatile("cp.async.wait_group 1;" ::: "memory");
        } else {
            asm volatile("cp.async.wait_group 0;" ::: "memory");
        }
        __syncthreads();

        const bf16* As = (const bf16*)(smr + cur*PJ_A_SZ);
        const bf16* Bs = (const bf16*)(smr + PJ_B_OFF + cur*PJ_B_SZ);
        #pragma unroll
        for(int ks=0;ks<4;ks++){
            u32 af[2][4];
            #pragma unroll
            for(int mf=0;mf<2;mf++){
                const bf16* ar = As + (w*32 + mf*16 + g)*72 + ks*16 + 2*tig;
                af[mf][0] = *(const u32*)ar;
                af[mf][1] = *(const u32*)(ar + 8*72);
                af[mf][2] = *(const u32*)(ar + 8);
                af[mf][3] = *(const u32*)(ar + 8*72 + 8);
            }
            #pragma unroll
            for(int bn=0;bn<8;bn++){
                const bf16* br = Bs + (bn*8 + g)*72 + ks*16 + 2*tig;
                u32 b0 = *(const u32*)br, b1 = *(const u32*)(br + 8);
                mma16816(acc[0][bn], af[0], b0, b1);
                mma16816(acc[1][bn], af[1], b0, b1);
            }
        }
    }

    if(yblk == 0){
        #pragma unroll
        for(int mf=0;mf<2;mf++){
            int r0g = m0 + w*32 + mf*16 + g;
            #pragma unroll
            for(int bn=0;bn<8;bn++){
                int o = bn*8 + 2*tig;
                bf16* base = (o<32) ? g_Qb : g_Kb;
                int oo = o & 31;
                *(u32*)(base + ((size_t)(b*HWN) + r0g    )*KCN + oo) = bf2(acc[mf][bn][0], acc[mf][bn][1]);
                *(u32*)(base + ((size_t)(b*HWN) + r0g + 8)*KCN + oo) = bf2(acc[mf][bn][2], acc[mf][bn][3]);
            }
        }
    } else if(yblk == 1){
        #pragma unroll
        for(int mf=0;mf<2;mf++){
            int r0g = m0 + w*32 + mf*16 + g;
            #pragma unroll
            for(int bn=0;bn<8;bn++){
                int o = bn*8 + 2*tig;
                float* base = (o<32) ? g_b1r : g_b2r;
                int oo = o & 31;
                float2 v0; v0.x = fmaxf(acc[mf][bn][0],0.f); v0.y = fmaxf(acc[mf][bn][1],0.f);
                float2 v1; v1.x = fmaxf(acc[mf][bn][2],0.f); v1.y = fmaxf(acc[mf][bn][3],0.f);
                *(float2*)(base + ((size_t)(b*HWN) + r0g    )*KCN + oo) = v0;
                *(float2*)(base + ((size_t)(b*HWN) + r0g + 8)*KCN + oo) = v1;
            }
        }
    } else {
        __syncthreads();
        float* smf = (float*)smr;         // [64][132]
        #pragma unroll
        for(int mf=0;mf<2;mf++){
            int rl = w*32 + mf*16 + g;
            #pragma unroll
            for(int bn=0;bn<8;bn++){
                int col = bn*8 + 2*tig;
                smf[col*132 + rl]         = acc[mf][bn][0];
                smf[(col+1)*132 + rl]     = acc[mf][bn][1];
                smf[col*132 + rl + 8]     = acc[mf][bn][2];
                smf[(col+1)*132 + rl + 8] = acc[mf][bn][3];
            }
        }
        __syncthreads();
        int cc = t >> 1, half = t & 1;
        int c = (yblk-2)*64 + cc;
        bf16* dst = g_Vb + ((size_t)(b*CC) + c)*HWN + m0 + half*64;
        u32 pk[32];
        #pragma unroll
        for(int j=0;j<32;j++)
            pk[j] = bf2(smf[cc*132 + half*64 + 2*j], smf[cc*132 + half*64 + 2*j + 1]);
        #pragma unroll
        for(int q=0;q<8;q++) ((uint4*)dst)[q] = ((uint4*)pk)[q];
    }
}

// ---------------- 5) 3-tap box smoothing ([m][k] layout) ----------------
__global__ void k_smooth(){
    int idx = blockIdx.x*256 + threadIdx.x;
    int k = idx & 31;
    int m = (idx >> 5) & (HWN-1);
    int b = idx >> 17;
    size_t base = ((size_t)(b*HWN) + m)*KCN + k;
    float a1 = g_b1r[base], a2 = g_b2r[base];
    if(m > 0)      { a1 += g_b1r[base-KCN]; a2 += g_b2r[base-KCN]; }
    if(m < HWN-1)  { a1 += g_b1r[base+KCN]; a2 += g_b2r[base+KCN]; }
    g_b1b[base] = __float2bfloat16(a1);
    g_b2b[base] = __float2bfloat16(a2);
}

// ---------------- 6) fused attention: HMMA, 8 warps (2/SMSP), key-split pairs ---
// smem: V 2x[256][72 bf16] | K 2x[64][40 bf16] | B2 2x[64][40 bf16]
#define VT_SZ    36864
#define KT_OFF   73728
#define KT_SZ    5120
#define B2_OFF   83968
#define B2_SZ    5120
#define ATTN_SMEM 94208

__device__ __forceinline__ void attn_prefetch(u32 sb, int t, int b, int key0, int buf){
    #pragma unroll
    for(int u=0;u<8;u++){
        int ch = t + u*256;                 // 2048: 256 rows x 8
        int row = ch>>3, j = ch&7;
        cpa16(sb + (u32)(buf*VT_SZ + row*144 + j*16),
              g_Vb + ((size_t)b*CC + row)*HWN + key0 + j*8);
    }
    {
        int key = t>>2, j = t&3;            // 256: 64 rows x 4
        cpa16(sb + (u32)(KT_OFF + buf*KT_SZ + key*80 + j*16),
              g_Kb + ((size_t)(b*HWN) + key0 + key)*KCN + j*8);
        cpa16(sb + (u32)(B2_OFF + buf*B2_SZ + key*80 + j*16),
              g_b2b + ((size_t)(b*HWN) + key0 + key)*KCN + j*8);
    }
}

__global__ void __launch_bounds__(256,1) k_attn(const float* __restrict__ wgb){
    extern __shared__ char smr[];
    const u32 sb = (u32)__cvta_generic_to_shared(smr);
    const int t    = threadIdx.x;
    const int w    = t >> 5;
    const int wm   = w & 3;        // row-block warp
    const int kh   = w >> 2;       // key half (0: keys 0-31, 1: keys 32-63 of tile)
    const int lane = t & 31;
    const int g    = lane >> 2;
    const int tig  = lane & 3;
    const int b    = blockIdx.y;
    const int row0 = blockIdx.x*64 + wm*16;

    attn_prefetch(sb, t, b, 0, 0);
    cpa_commit();

    // Q / B1 fragments (bf16 direct); per-row, independent of key half
    u32 qf[2][4], b1f[2][4];
    {
        const bf16* q0 = g_Qb  + ((size_t)(b*HWN) + row0 + g)*KCN;
        const bf16* c0 = g_b1b + ((size_t)(b*HWN) + row0 + g)*KCN;
        #pragma unroll
        for(int ks=0;ks<2;ks++){
            qf[ks][0]  = *(const u32*)(q0 + ks*16 + 2*tig);
            qf[ks][1]  = *(const u32*)(q0 + 8*KCN + ks*16 + 2*tig);
            qf[ks][2]  = *(const u32*)(q0 + ks*16 + 2*tig + 8);
            qf[ks][3]  = *(const u32*)(q0 + 8*KCN + ks*16 + 2*tig + 8);
            b1f[ks][0] = *(const u32*)(c0 + ks*16 + 2*tig);
            b1f[ks][1] = *(const u32*)(c0 + 8*KCN + ks*16 + 2*tig);
            b1f[ks][2] = *(const u32*)(c0 + ks*16 + 2*tig + 8);
            b1f[ks][3] = *(const u32*)(c0 + 8*KCN + ks*16 + 2*tig + 8);
        }
    }

    float pv[32][4];
    #pragma unroll
    for(int i=0;i<32;i++){ pv[i][0]=0.f; pv[i][1]=0.f; pv[i][2]=0.f; pv[i][3]=0.f; }
    float ls0 = 0.f, ls1 = 0.f;
    const float cgb = wgb[0] * (1.0f/9.0f);

    for(int tile=0; tile<HWN/64; tile++){
        const int cur = tile & 1;
        __syncthreads();
        if(tile+1 < HWN/64){
            attn_prefetch(sb, t, b, (tile+1)*64, 1-cur);
            cpa_commit();
            asm volatile("cp.async.wait_group 1;" ::: "memory");
        } else {
            asm volatile("cp.async.wait_group 0;" ::: "memory");
        }
        __syncthreads();

        const bf16* Ks  = (const bf16*)(smr + KT_OFF + cur*KT_SZ);
        const bf16* B2s = (const bf16*)(smr + B2_OFF + cur*B2_SZ);
        const bf16* Vs  = (const bf16*)(smr + cur*VT_SZ);

        // ---- logits for this warp's 4 n-blocks (keys kh*32 .. kh*32+31) ----
        u32 pa[4][2];
        #pragma unroll
        for(int nt=0; nt<4; nt++){
            int gnt = kh*4 + nt;
            float sa[4] = {0.f,0.f,0.f,0.f};
            float pl[4] = {0.f,0.f,0.f,0.f};
            const bf16* kr = Ks  + (gnt*8 + g)*40;
            const bf16* br = B2s + (gnt*8 + g)*40;
            #pragma unroll
            for(int ks=0;ks<2;ks++){
                u32 k0  = *(const u32*)(kr + ks*16 + 2*tig);
                u32 k1  = *(const u32*)(kr + ks*16 + 2*tig + 8);
                u32 bb0 = *(const u32*)(br + ks*16 + 2*tig);
                u32 bb1 = *(const u32*)(br + ks*16 + 2*tig + 8);
                mma16816(sa, qf[ks],  k0,  k1);
                mma16816(pl, b1f[ks], bb0, bb1);
            }
            float e0 = __expf(sa[0] * sigm(cgb*pl[0]));
            float e1 = __expf(sa[1] * sigm(cgb*pl[1]));
            float e2 = __expf(sa[2] * sigm(cgb*pl[2]));
            float e3 = __expf(sa[3] * sigm(cgb*pl[3]));
            ls0 += e0 + e1;
            ls1 += e2 + e3;
            pa[nt][0] = bf2(e0, e1);
            pa[nt][1] = bf2(e2, e3);
        }

        // ---- partial PV over this warp's 32 keys ----
        #pragma unroll
        for(int cnt=0; cnt<32; cnt++){
            const bf16* vr = Vs + (cnt*8 + g)*72 + kh*32;
            #pragma unroll
            for(int ks=0;ks<2;ks++){
                u32 v0 = *(const u32*)(vr + 16*ks + 2*tig);
                u32 v1 = *(const u32*)(vr + 16*ks + 2*tig + 8);
                u32 af[4] = { pa[2*ks][0], pa[2*ks][1], pa[2*ks+1][0], pa[2*ks+1][1] };
                mma16816(pv[cnt], af, v0, v1);
            }
        }
    }

    // quad-reduce exp-sum partials (within this warp's key half)
    #pragma unroll
    for(int o=1;o<4;o<<=1){
        ls0 += __shfl_xor_sync(0xffffffffu, ls0, o);
        ls1 += __shfl_xor_sync(0xffffffffu, ls1, o);
    }

    // ---- combine warp pairs (w and w+4) via smem ----
    __syncthreads();                // all warps done reading V smem
    float* smf = (float*)smr;       // [4*32][131]: 128 pv + 2 ls
    if(kh == 1){
        float* dst = smf + (size_t)(wm*32 + lane)*131;
        #pragma unroll
        for(int cnt=0;cnt<32;cnt++){
            dst[cnt*4+0] = pv[cnt][0]; dst[cnt*4+1] = pv[cnt][1];
            dst[cnt*4+2] = pv[cnt][2]; dst[cnt*4+3] = pv[cnt][3];
        }
        dst[128] = ls0; dst[129] = ls1;
    }
    __syncthreads();
    if(kh == 0){
        const float* src = smf + (size_t)(wm*32 + lane)*131;
        #pragma unroll
        for(int cnt=0;cnt<32;cnt++){
            pv[cnt][0] += src[cnt*4+0]; pv[cnt][1] += src[cnt*4+1];
            pv[cnt][2] += src[cnt*4+2]; pv[cnt][3] += src[cnt*4+3];
        }
        ls0 += src[128]; ls1 += src[129];

        float rl0 = __fdividef(1.0f, ls0);
        float rl1 = __fdividef(1.0f, ls1);
        u32* d0 = (u32*)(g_ctxb + ((size_t)(b*HWN) + row0 + g    )*CC);
        u32* d8 = (u32*)(g_ctxb + ((size_t)(b*HWN) + row0 + g + 8)*CC);
        #pragma unroll
        for(int cnt=0; cnt<32; cnt++){
            d0[cnt*4 + tig] = bf2(pv[cnt][0]*rl0, pv[cnt][1]*rl0);
            d8[cnt*4 + tig] = bf2(pv[cnt][2]*rl1, pv[cnt][3]*rl1);
        }
    }
}

// ---------------- 7) output projection (HMMA) + BN + ReLU + residual ----------
__global__ void __launch_bounds__(128,1) k_final(
    const float* __restrict__ x,
    const float* __restrict__ bn_scale, const float* __restrict__ bn_bias,
    const float* __restrict__ bn_mean, const float* __restrict__ bn_var,
    const float* __restrict__ gamma, float* __restrict__ out)
{
    extern __shared__ char smr[];
    const u32 sb = (u32)__cvta_generic_to_shared(smr);
    const int t    = threadIdx.x;
    const int w    = t >> 5;
    const int lane = t & 31;
    const int g    = lane >> 2;
    const int tig  = lane & 3;
    const int b    = blockIdx.z;
    const int c0   = blockIdx.y*64;
    const int m0   = blockIdx.x*128;

    const bf16* asrc = g_ctxb + ((size_t)(b*HWN) + m0)*CC;
    const bf16* bsrc = g_Wob + (size_t)c0*CC;

    float acc[2][8][4];
    #pragma unroll
    for(int mf=0;mf<2;mf++)
        #pragma unroll
        for(int bn=0;bn<8;bn++)
            #pragma unroll
            for(int q=0;q<4;q++) acc[mf][bn][q]=0.f;

    {
        #pragma unroll
        for(int u=0;u<8;u++){
            int ch = t + u*128;
            int row = ch>>3, j = ch&7;
            cpa16(sb + (u32)(row*144 + j*16), asrc + (size_t)row*CC + j*8);
        }
        #pragma unroll
        for(int u=0;u<4;u++){
            int ch = t + u*128;
            int row = ch>>3, j = ch&7;
            cpa16(sb + PJ_B_OFF + (u32)(row*144 + j*16), bsrc + (size_t)row*CC + j*8);
        }
        cpa_commit();
    }

    for(int cc=0; cc<4; cc++){
        const int cur = cc & 1;
        __syncthreads();
        if(cc+1 < 4){
            const int nb = 1-cur;
            #pragma unroll
            for(int u=0;u<8;u++){
                int ch = t + u*128;
                int row = ch>>3, j = ch&7;
                cpa16(sb + (u32)(nb*PJ_A_SZ + row*144 + j*16),
                      asrc + (size_t)row*CC + (cc+1)*64 + j*8);
            }
            #pragma unroll
            for(int u=0;u<4;u++){
                int ch = t + u*128;
                int row = ch>>3, j = ch&7;
                cpa16(sb + (u32)(PJ_B_OFF + nb*PJ_B_SZ + row*144 + j*16),
                      bsrc + (size_t)row*CC + (cc+1)*64 + j*8);
            }
            cpa_commit();
            asm volatile("cp.async.wait_group 1;" ::: "memory");
        } else {
            asm volatile("cp.async.wait_group 0;" ::: "memory");
        }
        __syncthreads();

        const bf16* As = (const bf16*)(smr + cur*PJ_A_SZ);
        const bf16* Bs = (const bf16*)(smr + PJ_B_OFF + cur*PJ_B_SZ);
        #pragma unroll
        for(int ks=0;ks<4;ks++){
            u32 af[2][4];
            #pragma unroll
            for(int mf=0;mf<2;mf++){
                const bf16* ar = As + (w*32 + mf*16 + g)*72 + ks*16 + 2*tig;
                af[mf][0] = *(const u32*)ar;
                af[mf][1] = *(const u32*)(ar + 8*72);
                af[mf][2] = *(const u32*)(ar + 8);
                af[mf][3] = *(const u32*)(ar + 8*72 + 8);
            }
            #pragma unroll
            for(int bn=0;bn<8;bn++){
                const bf16* br = Bs + (bn*8 + g)*72 + ks*16 + 2*tig;
                u32 b0 = *(const u32*)br, b1 = *(const u32*)(br + 8);
                mma16816(acc[0][bn], af[0], b0, b1);
                mma16816(acc[1][bn], af[1], b0, b1);
            }
        }
    }

    __syncthreads();
    float* smf = (float*)smr;   // [64][132]
    #pragma unroll
    for(int mf=0;mf<2;mf++){
        int rl = w*32 + mf*16 + g;
        #pragma unroll
        for(int bn=0;bn<8;bn++){
            int col = bn*8 + 2*tig;
            smf[col*132 + rl]         = acc[mf][bn][0];
            smf[(col+1)*132 + rl]     = acc[mf][bn][1];
            smf[col*132 + rl + 8]     = acc[mf][bn][2];
            smf[(col+1)*132 + rl + 8] = acc[mf][bn][3];
        }
    }
    __syncthreads();
    {
        int cc = t >> 1, half = t & 1;
        int c = c0 + cc;
        float scl = bn_scale[c] * rsqrtf(bn_var[c] + EPSV);
        float mu  = bn_mean[c];
        float bi  = bn_bias[c];
        float gm  = gamma[0];
        const float* xr = x   + ((size_t)(b*CC) + c)*HWN + m0 + half*64;
        float* orow     = out + ((size_t)(b*CC) + c)*HWN + m0 + half*64;
        #pragma unroll
        for(int q=0;q<16;q++){
            float4 xv = *(const float4*)(xr + q*4);
            float4 o;
            float v0 = smf[cc*132 + half*64 + q*4 + 0];
            float v1 = smf[cc*132 + half*64 + q*4 + 1];
            float v2 = smf[cc*132 + half*64 + q*4 + 2];
            float v3 = smf[cc*132 + half*64 + q*4 + 3];
            o.x = gm*fmaxf((v0-mu)*scl+bi, 0.f) + xv.x;
            o.y = gm*fmaxf((v1-mu)*scl+bi, 0.f) + xv.y;
            o.z = gm*fmaxf((v2-mu)*scl+bi, 0.f) + xv.z;
            o.w = gm*fmaxf((v3-mu)*scl+bi, 0.f) + xv.w;
            *(float4*)(orow + q*4) = o;
        }
    }
}

// ---------------- launch ----------------
extern "C" void kernel_launch(void* const* d_in, const int* in_sizes, int n_in,
                              void* d_out, int out_size){
    (void)in_sizes; (void)n_in; (void)out_size;
    const float* x        = (const float*)d_in[0];
    const float* Wq       = (const float*)d_in[1];
    const float* Wk       = (const float*)d_in[2];
    const float* Wv       = (const float*)d_in[3];
    const float* Wb1      = (const float*)d_in[4];
    const float* Wb2      = (const float*)d_in[5];
    const float* w_gb     = (const float*)d_in[6];
    const float* ge_w1    = (const float*)d_in[7];
    const float* ge_b1    = (const float*)d_in[8];
    const float* ge_w2    = (const float*)d_in[9];
    const float* ge_b2    = (const float*)d_in[10];
    const float* Wo       = (const float*)d_in[11];
    const float* bn_scale = (const float*)d_in[12];
    const float* bn_bias  = (const float*)d_in[13];
    const float* bn_mean  = (const float*)d_in[14];
    const float* bn_var   = (const float*)d_in[15];
    const float* gamma    = (const float*)d_in[16];
    float* out = (float*)d_out;

    cudaFuncSetAttribute(k_attn,   cudaFuncAttributeMaxDynamicSharedMemorySize, ATTN_SMEM);
    cudaFuncSetAttribute(k_projmm, cudaFuncAttributeMaxDynamicSharedMemorySize, PJ_SMEM);
    cudaFuncSetAttribute(k_final,  cudaFuncAttributeMaxDynamicSharedMemorySize, PJ_SMEM);

    k_mean  <<<dim3(CC/8, BB), 256>>>(x);
    k_gate  <<<BB, 256>>>(ge_w1, ge_b1, ge_w2, ge_b2);
    k_xpose <<<dim3(HWN/128, CC/32, BB), 128>>>(x);
    k_wprep <<<(BB*NO*CC + CC*CC)/256, 256>>>(Wq, Wk, Wb1, Wb2, Wv, Wo);
    k_projmm<<<dim3(HWN/128, NO/64, BB), 128, PJ_SMEM>>>();
    k_smooth<<<(BB*HWN*KCN)/256, 256>>>();
    k_attn  <<<dim3(HWN/64, BB), 256, ATTN_SMEM>>>(w_gb);
    k_final <<<dim3(HWN/128, CC/64, BB), 128, PJ_SMEM>>>(x, bn_scale, bn_bias,
                                                         bn_mean, bn_var, gamma, out);
}